// round 3
// baseline (speedup 1.0000x reference)
#include <cuda_runtime.h>
#include <math.h>

#define S_LEN 2048
#define HID   4096
#define NH    32
#define NKV   8
#define HD    128

// -------- scratch (device globals; no allocation allowed) --------
__device__ float g_Q[S_LEN * NH * HD];     // 32 MB
__device__ float g_K[S_LEN * NKV * HD];    // 8 MB
__device__ float g_V[S_LEN * NKV * HD];    // 8 MB
__device__ float g_attn[S_LEN * NH * HD];  // 32 MB

// ================= SGEMM: C[M,N] = A[M,K] @ B[K,N], row-major =================
// 128x128 block tile, BK=8, 256 threads, 8x8 per-thread micro-tile.
// Double-buffered smem: one __syncthreads per k-tile, loads overlap compute.
__global__ __launch_bounds__(256, 2)
void sgemm128x128(const float* __restrict__ A, const float* __restrict__ B,
                  float* __restrict__ C, int M, int N, int K)
{
    __shared__ float As[2][8][128];   // A staged transposed: As[buf][k][m]
    __shared__ float Bs[2][8][128];

    const int tid = threadIdx.x;
    const int tx = tid & 15, ty = tid >> 4;
    const int bn = blockIdx.x, bm = blockIdx.y;

    const float* Ab = A + (size_t)bm * 128 * K;
    const float* Bb = B + (size_t)bn * 128;

    const int arow = tid >> 1, acol = (tid & 1) * 4;
    const int brow = tid >> 5, bcol = (tid & 31) * 4;

    float acc[8][8];
#pragma unroll
    for (int i = 0; i < 8; i++)
#pragma unroll
        for (int j = 0; j < 8; j++) acc[i][j] = 0.f;

    // ---- preload tile 0 into buffer 0 ----
    {
        float4 av = *(const float4*)(Ab + (size_t)arow * K + acol);
        float4 bv = *(const float4*)(Bb + (size_t)brow * N + bcol);
        As[0][acol + 0][arow] = av.x;
        As[0][acol + 1][arow] = av.y;
        As[0][acol + 2][arow] = av.z;
        As[0][acol + 3][arow] = av.w;
        *(float4*)&Bs[0][brow][bcol] = bv;
    }
    __syncthreads();

    int buf = 0;
    for (int kt = 8; kt < K; kt += 8) {
        // issue next tile's loads early (latency hidden behind FMAs below)
        float4 av = *(const float4*)(Ab + (size_t)arow * K + kt + acol);
        float4 bv = *(const float4*)(Bb + (size_t)(kt + brow) * N + bcol);

        // compute on current buffer
#pragma unroll
        for (int k = 0; k < 8; k++) {
            float a[8], b[8];
            *(float4*)(a)     = *(const float4*)&As[buf][k][ty * 8];
            *(float4*)(a + 4) = *(const float4*)&As[buf][k][ty * 8 + 4];
            *(float4*)(b)     = *(const float4*)&Bs[buf][k][tx * 8];
            *(float4*)(b + 4) = *(const float4*)&Bs[buf][k][tx * 8 + 4];
#pragma unroll
            for (int i = 0; i < 8; i++)
#pragma unroll
                for (int j = 0; j < 8; j++)
                    acc[i][j] = fmaf(a[i], b[j], acc[i][j]);
        }

        // stage next tile into the other buffer
        As[buf ^ 1][acol + 0][arow] = av.x;
        As[buf ^ 1][acol + 1][arow] = av.y;
        As[buf ^ 1][acol + 2][arow] = av.z;
        As[buf ^ 1][acol + 3][arow] = av.w;
        *(float4*)&Bs[buf ^ 1][brow][bcol] = bv;
        __syncthreads();
        buf ^= 1;
    }

    // ---- last tile ----
#pragma unroll
    for (int k = 0; k < 8; k++) {
        float a[8], b[8];
        *(float4*)(a)     = *(const float4*)&As[buf][k][ty * 8];
        *(float4*)(a + 4) = *(const float4*)&As[buf][k][ty * 8 + 4];
        *(float4*)(b)     = *(const float4*)&Bs[buf][k][tx * 8];
        *(float4*)(b + 4) = *(const float4*)&Bs[buf][k][tx * 8 + 4];
#pragma unroll
        for (int i = 0; i < 8; i++)
#pragma unroll
            for (int j = 0; j < 8; j++)
                acc[i][j] = fmaf(a[i], b[j], acc[i][j]);
    }

#pragma unroll
    for (int i = 0; i < 8; i++) {
        float* Cr = C + (size_t)(bm * 128 + ty * 8 + i) * N + bn * 128 + tx * 8;
        *(float4*)(Cr)     = make_float4(acc[i][0], acc[i][1], acc[i][2], acc[i][3]);
        *(float4*)(Cr + 4) = make_float4(acc[i][4], acc[i][5], acc[i][6], acc[i][7]);
    }
}

// ================= llama3-smoothed RoPE, in place =================
// x layout: [S][nheads*HD]; pair (i, i+64) rotated per head.
__global__ void rope_kernel(float* __restrict__ x, int nheads)
{
    int idx = blockIdx.x * blockDim.x + threadIdx.x;
    int total = S_LEN * nheads * (HD / 2);
    if (idx >= total) return;
    int i = idx & 63;
    int h = (idx >> 6) % nheads;
    int s = idx / (64 * nheads);

    // frequencies in double for stability, then fp32 like the reference
    double inv_freq = exp(-((double)(2 * i) / (double)HD) * log(500000.0));
    double wavelen  = (2.0 * 3.14159265358979323846) / inv_freq;
    double smooth   = (8192.0 / wavelen - 1.0) / (4.0 - 1.0);
    smooth = fmin(1.0, fmax(0.0, smooth));
    double nf = (1.0 - smooth) * (inv_freq / 8.0) + smooth * inv_freq;

    float freq = (float)nf;
    float ang  = (float)s * freq;
    float c, sn;
    sincosf(ang, &sn, &c);

    float* row = x + (size_t)s * nheads * HD + h * HD;
    float x1 = row[i], x2 = row[i + 64];
    row[i]      = x1 * c - x2 * sn;
    row[i + 64] = x2 * c + x1 * sn;
}

// ================= Flash attention (causal, GQA) =================
// grid: (32 q-tiles, 32 heads), 256 threads. BQ=BK=64.
// smem: Qs[64][132], KVs[64][132] (K then V reuse), Ps[64][65]
#define BQ 64
#define BKV 64
#define KSTR 132
#define PSTR 65

__global__ __launch_bounds__(256, 1)
void flash_kernel(const float* __restrict__ Q, const float* __restrict__ K,
                  const float* __restrict__ V, float* __restrict__ O)
{
    extern __shared__ float sm[];
    float* Qs  = sm;                       // [64][132]
    float* KVs = sm + 64 * KSTR;           // [64][132]
    float* Ps  = sm + 2 * 64 * KSTR;       // [64][65]

    const int qt  = gridDim.x - 1 - blockIdx.x;   // longest blocks first
    const int h   = blockIdx.y;
    const int kvh = h >> 2;                       // G = NH/NKV = 4
    const int tid = threadIdx.x;
    const int tx = tid & 15, ty = tid >> 4;
    const int q0 = qt * BQ;
    const float scale = 0.08838834764831845f;     // 1/sqrt(128)

    // load Q tile (coalesced float4)
    for (int t = tid; t < 64 * 32; t += 256) {
        int r = t >> 5, c4 = (t & 31) << 2;
        *(float4*)&Qs[r * KSTR + c4] =
            *(const float4*)&Q[(size_t)(q0 + r) * (NH * HD) + h * HD + c4];
    }

    float m_i[4], l_i[4], o_acc[4][8];
#pragma unroll
    for (int i = 0; i < 4; i++) {
        m_i[i] = -INFINITY;
        l_i[i] = 0.f;
#pragma unroll
        for (int j = 0; j < 8; j++) o_acc[i][j] = 0.f;
    }

    for (int j = 0; j <= qt; j++) {
        const int k0 = j * BKV;
        __syncthreads();   // prev PV done reading KVs; Qs ready (iter 0)
        for (int t = tid; t < 64 * 32; t += 256) {
            int r = t >> 5, c4 = (t & 31) << 2;
            *(float4*)&KVs[r * KSTR + c4] =
                *(const float4*)&K[(size_t)(k0 + r) * (NKV * HD) + kvh * HD + c4];
        }
        __syncthreads();

        // ---- S = Q K^T (4x4 per thread) ----
        float sacc[4][4];
#pragma unroll
        for (int i = 0; i < 4; i++)
#pragma unroll
            for (int jj = 0; jj < 4; jj++) sacc[i][jj] = 0.f;

#pragma unroll 8
        for (int d = 0; d < HD; d += 4) {
            float4 qa[4], kb[4];
#pragma unroll
            for (int i = 0; i < 4; i++)
                qa[i] = *(const float4*)&Qs[(ty * 4 + i) * KSTR + d];
#pragma unroll
            for (int i = 0; i < 4; i++)
                kb[i] = *(const float4*)&KVs[(tx * 4 + i) * KSTR + d];
#pragma unroll
            for (int i = 0; i < 4; i++)
#pragma unroll
                for (int jj = 0; jj < 4; jj++) {
                    sacc[i][jj] = fmaf(qa[i].x, kb[jj].x, sacc[i][jj]);
                    sacc[i][jj] = fmaf(qa[i].y, kb[jj].y, sacc[i][jj]);
                    sacc[i][jj] = fmaf(qa[i].z, kb[jj].z, sacc[i][jj]);
                    sacc[i][jj] = fmaf(qa[i].w, kb[jj].w, sacc[i][jj]);
                }
        }

        // ---- scale + causal mask (diagonal tile only) ----
        const bool diag = (j == qt);
#pragma unroll
        for (int i = 0; i < 4; i++)
#pragma unroll
            for (int jj = 0; jj < 4; jj++) {
                float v = sacc[i][jj] * scale;
                if (diag && (k0 + tx * 4 + jj) > (q0 + ty * 4 + i)) v = -INFINITY;
                sacc[i][jj] = v;
            }

        // ---- online softmax ----
        float mt[4], mn[4], alpha[4], rs[4];
#pragma unroll
        for (int i = 0; i < 4; i++) {
            mt[i] = fmaxf(fmaxf(sacc[i][0], sacc[i][1]), fmaxf(sacc[i][2], sacc[i][3]));
#pragma unroll
            for (int off = 8; off >= 1; off >>= 1)
                mt[i] = fmaxf(mt[i], __shfl_xor_sync(0xffffffffu, mt[i], off, 16));
            mn[i]    = fmaxf(m_i[i], mt[i]);
            alpha[i] = expf(m_i[i] - mn[i]);
            float lsum = 0.f;
#pragma unroll
            for (int jj = 0; jj < 4; jj++) {
                float p = expf(sacc[i][jj] - mn[i]);
                sacc[i][jj] = p;
                lsum += p;
            }
#pragma unroll
            for (int off = 8; off >= 1; off >>= 1)
                lsum += __shfl_xor_sync(0xffffffffu, lsum, off, 16);
            rs[i] = lsum;
        }
#pragma unroll
        for (int i = 0; i < 4; i++) {
            l_i[i] = l_i[i] * alpha[i] + rs[i];
            m_i[i] = mn[i];
#pragma unroll
            for (int jj = 0; jj < 8; jj++) o_acc[i][jj] *= alpha[i];
            // write P
#pragma unroll
            for (int jj = 0; jj < 4; jj++)
                Ps[(ty * 4 + i) * PSTR + tx * 4 + jj] = sacc[i][jj];
        }
        __syncthreads();   // Ps visible; all K reads done

        // ---- load V over KVs ----
        for (int t = tid; t < 64 * 32; t += 256) {
            int r = t >> 5, c4 = (t & 31) << 2;
            *(float4*)&KVs[r * KSTR + c4] =
                *(const float4*)&V[(size_t)(k0 + r) * (NKV * HD) + kvh * HD + c4];
        }
        __syncthreads();

        // ---- O += P @ V ----
#pragma unroll 4
        for (int c = 0; c < BKV; c++) {
            float4 v0 = *(const float4*)&KVs[c * KSTR + tx * 8];
            float4 v1 = *(const float4*)&KVs[c * KSTR + tx * 8 + 4];
#pragma unroll
            for (int i = 0; i < 4; i++) {
                float p = Ps[(ty * 4 + i) * PSTR + c];
                o_acc[i][0] = fmaf(p, v0.x, o_acc[i][0]);
                o_acc[i][1] = fmaf(p, v0.y, o_acc[i][1]);
                o_acc[i][2] = fmaf(p, v0.z, o_acc[i][2]);
                o_acc[i][3] = fmaf(p, v0.w, o_acc[i][3]);
                o_acc[i][4] = fmaf(p, v1.x, o_acc[i][4]);
                o_acc[i][5] = fmaf(p, v1.y, o_acc[i][5]);
                o_acc[i][6] = fmaf(p, v1.z, o_acc[i][6]);
                o_acc[i][7] = fmaf(p, v1.w, o_acc[i][7]);
            }
        }
    }

    // ---- epilogue: O / l ----
#pragma unroll
    for (int i = 0; i < 4; i++) {
        float inv = 1.f / l_i[i];
        float* Orow = O + (size_t)(q0 + ty * 4 + i) * (NH * HD) + h * HD + tx * 8;
        *(float4*)(Orow)     = make_float4(o_acc[i][0] * inv, o_acc[i][1] * inv,
                                           o_acc[i][2] * inv, o_acc[i][3] * inv);
        *(float4*)(Orow + 4) = make_float4(o_acc[i][4] * inv, o_acc[i][5] * inv,
                                           o_acc[i][6] * inv, o_acc[i][7] * inv);
    }
}

// ================= launcher =================
extern "C" void kernel_launch(void* const* d_in, const int* in_sizes, int n_in,
                              void* d_out, int out_size)
{
    const float* X  = (const float*)d_in[0];
    const float* Wq = (const float*)d_in[1];
    const float* Wk = (const float*)d_in[2];
    const float* Wv = (const float*)d_in[3];
    const float* Wo = (const float*)d_in[4];
    float* out = (float*)d_out;

    float *Qp, *Kp, *Vp, *Ap;
    cudaGetSymbolAddress((void**)&Qp, g_Q);
    cudaGetSymbolAddress((void**)&Kp, g_K);
    cudaGetSymbolAddress((void**)&Vp, g_V);
    cudaGetSymbolAddress((void**)&Ap, g_attn);

    dim3 blk(256);

    // QKV projections
    sgemm128x128<<<dim3((NH * HD) / 128, S_LEN / 128), blk>>>(X, Wq, Qp, S_LEN, NH * HD, HID);
    sgemm128x128<<<dim3((NKV * HD) / 128, S_LEN / 128), blk>>>(X, Wk, Kp, S_LEN, NKV * HD, HID);
    sgemm128x128<<<dim3((NKV * HD) / 128, S_LEN / 128), blk>>>(X, Wv, Vp, S_LEN, NKV * HD, HID);

    // RoPE on Q and K
    int tq = S_LEN * NH * (HD / 2);
    int tk = S_LEN * NKV * (HD / 2);
    rope_kernel<<<(tq + 255) / 256, 256>>>(Qp, NH);
    rope_kernel<<<(tk + 255) / 256, 256>>>(Kp, NKV);

    // flash attention
    const int smem = (2 * 64 * KSTR + 64 * PSTR) * (int)sizeof(float);  // 84224 B
    cudaFuncSetAttribute(flash_kernel, cudaFuncAttributeMaxDynamicSharedMemorySize, smem);
    flash_kernel<<<dim3(S_LEN / BQ, NH), blk, smem>>>(Qp, Kp, Vp, Ap);

    // output projection
    sgemm128x128<<<dim3(HID / 128, S_LEN / 128), blk>>>(Ap, Wo, out, S_LEN, HID, HID);
}

// round 4
// speedup vs baseline: 1.1141x; 1.1141x over previous
#include <cuda_runtime.h>
#include <math.h>

#define S_LEN 2048
#define HID   4096
#define NH    32
#define NKV   8
#define HD    128

// -------- scratch (device globals; no allocation allowed) --------
__device__ float g_Q[S_LEN * NH * HD];     // 32 MB
__device__ float g_K[S_LEN * NKV * HD];    // 8 MB
__device__ float g_V[S_LEN * NKV * HD];    // 8 MB
__device__ float g_attn[S_LEN * NH * HD];  // 32 MB

// ================= SGEMM: C[M,N] = A[M,K] @ B[K,N], row-major =================
// 128x128 block tile, BK=8, 256 threads, 8x8 per-thread micro-tile.
// Double-buffered smem: one __syncthreads per k-tile, loads overlap compute.
__global__ __launch_bounds__(256, 2)
void sgemm128x128(const float* __restrict__ A, const float* __restrict__ B,
                  float* __restrict__ C, int M, int N, int K)
{
    __shared__ float As[2][8][128];   // A staged transposed: As[buf][k][m]
    __shared__ float Bs[2][8][128];

    const int tid = threadIdx.x;
    const int tx = tid & 15, ty = tid >> 4;
    const int bn = blockIdx.x, bm = blockIdx.y;

    const float* Ab = A + (size_t)bm * 128 * K;
    const float* Bb = B + (size_t)bn * 128;

    const int arow = tid >> 1, acol = (tid & 1) * 4;
    const int brow = tid >> 5, bcol = (tid & 31) * 4;

    float acc[8][8];
#pragma unroll
    for (int i = 0; i < 8; i++)
#pragma unroll
        for (int j = 0; j < 8; j++) acc[i][j] = 0.f;

    // ---- preload tile 0 into buffer 0 ----
    {
        float4 av = *(const float4*)(Ab + (size_t)arow * K + acol);
        float4 bv = *(const float4*)(Bb + (size_t)brow * N + bcol);
        As[0][acol + 0][arow] = av.x;
        As[0][acol + 1][arow] = av.y;
        As[0][acol + 2][arow] = av.z;
        As[0][acol + 3][arow] = av.w;
        *(float4*)&Bs[0][brow][bcol] = bv;
    }
    __syncthreads();

    int buf = 0;
    for (int kt = 8; kt < K; kt += 8) {
        // issue next tile's loads early (latency hidden behind FMAs below)
        float4 av = *(const float4*)(Ab + (size_t)arow * K + kt + acol);
        float4 bv = *(const float4*)(Bb + (size_t)(kt + brow) * N + bcol);

        // compute on current buffer
#pragma unroll
        for (int k = 0; k < 8; k++) {
            float a[8], b[8];
            *(float4*)(a)     = *(const float4*)&As[buf][k][ty * 8];
            *(float4*)(a + 4) = *(const float4*)&As[buf][k][ty * 8 + 4];
            *(float4*)(b)     = *(const float4*)&Bs[buf][k][tx * 8];
            *(float4*)(b + 4) = *(const float4*)&Bs[buf][k][tx * 8 + 4];
#pragma unroll
            for (int i = 0; i < 8; i++)
#pragma unroll
                for (int j = 0; j < 8; j++)
                    acc[i][j] = fmaf(a[i], b[j], acc[i][j]);
        }

        // stage next tile into the other buffer
        As[buf ^ 1][acol + 0][arow] = av.x;
        As[buf ^ 1][acol + 1][arow] = av.y;
        As[buf ^ 1][acol + 2][arow] = av.z;
        As[buf ^ 1][acol + 3][arow] = av.w;
        *(float4*)&Bs[buf ^ 1][brow][bcol] = bv;
        __syncthreads();
        buf ^= 1;
    }

    // ---- last tile ----
#pragma unroll
    for (int k = 0; k < 8; k++) {
        float a[8], b[8];
        *(float4*)(a)     = *(const float4*)&As[buf][k][ty * 8];
        *(float4*)(a + 4) = *(const float4*)&As[buf][k][ty * 8 + 4];
        *(float4*)(b)     = *(const float4*)&Bs[buf][k][tx * 8];
        *(float4*)(b + 4) = *(const float4*)&Bs[buf][k][tx * 8 + 4];
#pragma unroll
        for (int i = 0; i < 8; i++)
#pragma unroll
            for (int j = 0; j < 8; j++)
                acc[i][j] = fmaf(a[i], b[j], acc[i][j]);
    }

#pragma unroll
    for (int i = 0; i < 8; i++) {
        float* Cr = C + (size_t)(bm * 128 + ty * 8 + i) * N + bn * 128 + tx * 8;
        *(float4*)(Cr)     = make_float4(acc[i][0], acc[i][1], acc[i][2], acc[i][3]);
        *(float4*)(Cr + 4) = make_float4(acc[i][4], acc[i][5], acc[i][6], acc[i][7]);
    }
}

// ================= llama3-smoothed RoPE, in place, fp32, float4 =================
// x layout: [S][nheads*HD]; pair (d, d+64) rotated per head.
// One thread handles 4 consecutive pairs (float4 at d, float4 at d+64).
__global__ __launch_bounds__(256)
void rope_kernel(float* __restrict__ x, int nheads)
{
    int idx = blockIdx.x * blockDim.x + threadIdx.x;
    int total = S_LEN * nheads * 16;           // 16 float4-pair groups per head
    if (idx >= total) return;
    int g = idx & 15;                          // which group of 4 pairs
    int h = (idx >> 4) % nheads;
    int s = idx / (16 * nheads);

    const float LOG2_BASE = 18.93156856932417f;   // log2(500000)
    const float TWO_PI    = 6.283185307179586f;

    float* row = x + (size_t)s * nheads * HD + h * HD;
    float4 v1 = *(float4*)&row[g * 4];
    float4 v2 = *(float4*)&row[g * 4 + 64];

    float o1[4], o2[4];
#pragma unroll
    for (int t = 0; t < 4; t++) {
        int i = g * 4 + t;
        // fp32 frequency derivation (matches the jnp float32 reference)
        float inv_freq = exp2f(-((float)(2 * i) / 128.0f) * LOG2_BASE);
        float wavelen  = TWO_PI / inv_freq;
        float smooth   = (8192.0f / wavelen - 1.0f) * (1.0f / 3.0f);
        smooth = fminf(1.0f, fmaxf(0.0f, smooth));
        float freq = (1.0f - smooth) * (inv_freq * 0.125f) + smooth * inv_freq;

        float c, sn;
        sincosf((float)s * freq, &sn, &c);
        float x1 = (&v1.x)[t], x2 = (&v2.x)[t];
        o1[t] = x1 * c - x2 * sn;
        o2[t] = x2 * c + x1 * sn;
    }
    *(float4*)&row[g * 4]      = make_float4(o1[0], o1[1], o1[2], o1[3]);
    *(float4*)&row[g * 4 + 64] = make_float4(o2[0], o2[1], o2[2], o2[3]);
}

// ================= Flash attention (causal, GQA) =================
// grid: (32 q-tiles, 32 heads), 256 threads. BQ=BK=64.
// smem: Qs[64][132], KVs[64][132] (K then V reuse), Ps[64][65]
#define BQ 64
#define BKV 64
#define KSTR 132
#define PSTR 65

__global__ __launch_bounds__(256, 1)
void flash_kernel(const float* __restrict__ Q, const float* __restrict__ K,
                  const float* __restrict__ V, float* __restrict__ O)
{
    extern __shared__ float sm[];
    float* Qs  = sm;                       // [64][132]
    float* KVs = sm + 64 * KSTR;           // [64][132]
    float* Ps  = sm + 2 * 64 * KSTR;       // [64][65]

    const int qt  = gridDim.x - 1 - blockIdx.x;   // longest blocks first
    const int h   = blockIdx.y;
    const int kvh = h >> 2;                       // G = NH/NKV = 4
    const int tid = threadIdx.x;
    const int tx = tid & 15, ty = tid >> 4;
    const int q0 = qt * BQ;
    const float scale = 0.08838834764831845f;     // 1/sqrt(128)

    // load Q tile (coalesced float4)
    for (int t = tid; t < 64 * 32; t += 256) {
        int r = t >> 5, c4 = (t & 31) << 2;
        *(float4*)&Qs[r * KSTR + c4] =
            *(const float4*)&Q[(size_t)(q0 + r) * (NH * HD) + h * HD + c4];
    }

    float m_i[4], l_i[4], o_acc[4][8];
#pragma unroll
    for (int i = 0; i < 4; i++) {
        m_i[i] = -INFINITY;
        l_i[i] = 0.f;
#pragma unroll
        for (int j = 0; j < 8; j++) o_acc[i][j] = 0.f;
    }

    for (int j = 0; j <= qt; j++) {
        const int k0 = j * BKV;
        __syncthreads();   // prev PV done reading KVs; Qs ready (iter 0)
        for (int t = tid; t < 64 * 32; t += 256) {
            int r = t >> 5, c4 = (t & 31) << 2;
            *(float4*)&KVs[r * KSTR + c4] =
                *(const float4*)&K[(size_t)(k0 + r) * (NKV * HD) + kvh * HD + c4];
        }
        __syncthreads();

        // ---- S = Q K^T (4x4 per thread) ----
        float sacc[4][4];
#pragma unroll
        for (int i = 0; i < 4; i++)
#pragma unroll
            for (int jj = 0; jj < 4; jj++) sacc[i][jj] = 0.f;

#pragma unroll 8
        for (int d = 0; d < HD; d += 4) {
            float4 qa[4], kb[4];
#pragma unroll
            for (int i = 0; i < 4; i++)
                qa[i] = *(const float4*)&Qs[(ty * 4 + i) * KSTR + d];
#pragma unroll
            for (int i = 0; i < 4; i++)
                kb[i] = *(const float4*)&KVs[(tx * 4 + i) * KSTR + d];
#pragma unroll
            for (int i = 0; i < 4; i++)
#pragma unroll
                for (int jj = 0; jj < 4; jj++) {
                    sacc[i][jj] = fmaf(qa[i].x, kb[jj].x, sacc[i][jj]);
                    sacc[i][jj] = fmaf(qa[i].y, kb[jj].y, sacc[i][jj]);
                    sacc[i][jj] = fmaf(qa[i].z, kb[jj].z, sacc[i][jj]);
                    sacc[i][jj] = fmaf(qa[i].w, kb[jj].w, sacc[i][jj]);
                }
        }

        // ---- scale + causal mask (diagonal tile only) ----
        const bool diag = (j == qt);
#pragma unroll
        for (int i = 0; i < 4; i++)
#pragma unroll
            for (int jj = 0; jj < 4; jj++) {
                float v = sacc[i][jj] * scale;
                if (diag && (k0 + tx * 4 + jj) > (q0 + ty * 4 + i)) v = -INFINITY;
                sacc[i][jj] = v;
            }

        // ---- online softmax ----
        float mt[4], mn[4], alpha[4], rs[4];
#pragma unroll
        for (int i = 0; i < 4; i++) {
            mt[i] = fmaxf(fmaxf(sacc[i][0], sacc[i][1]), fmaxf(sacc[i][2], sacc[i][3]));
#pragma unroll
            for (int off = 8; off >= 1; off >>= 1)
                mt[i] = fmaxf(mt[i], __shfl_xor_sync(0xffffffffu, mt[i], off, 16));
            mn[i]    = fmaxf(m_i[i], mt[i]);
            alpha[i] = expf(m_i[i] - mn[i]);
            float lsum = 0.f;
#pragma unroll
            for (int jj = 0; jj < 4; jj++) {
                float p = expf(sacc[i][jj] - mn[i]);
                sacc[i][jj] = p;
                lsum += p;
            }
#pragma unroll
            for (int off = 8; off >= 1; off >>= 1)
                lsum += __shfl_xor_sync(0xffffffffu, lsum, off, 16);
            rs[i] = lsum;
        }
#pragma unroll
        for (int i = 0; i < 4; i++) {
            l_i[i] = l_i[i] * alpha[i] + rs[i];
            m_i[i] = mn[i];
#pragma unroll
            for (int jj = 0; jj < 8; jj++) o_acc[i][jj] *= alpha[i];
            // write P
#pragma unroll
            for (int jj = 0; jj < 4; jj++)
                Ps[(ty * 4 + i) * PSTR + tx * 4 + jj] = sacc[i][jj];
        }
        __syncthreads();   // Ps visible; all K reads done

        // ---- load V over KVs ----
        for (int t = tid; t < 64 * 32; t += 256) {
            int r = t >> 5, c4 = (t & 31) << 2;
            *(float4*)&KVs[r * KSTR + c4] =
                *(const float4*)&V[(size_t)(k0 + r) * (NKV * HD) + kvh * HD + c4];
        }
        __syncthreads();

        // ---- O += P @ V ----
#pragma unroll 4
        for (int c = 0; c < BKV; c++) {
            float4 v0 = *(const float4*)&KVs[c * KSTR + tx * 8];
            float4 v1 = *(const float4*)&KVs[c * KSTR + tx * 8 + 4];
#pragma unroll
            for (int i = 0; i < 4; i++) {
                float p = Ps[(ty * 4 + i) * PSTR + c];
                o_acc[i][0] = fmaf(p, v0.x, o_acc[i][0]);
                o_acc[i][1] = fmaf(p, v0.y, o_acc[i][1]);
                o_acc[i][2] = fmaf(p, v0.z, o_acc[i][2]);
                o_acc[i][3] = fmaf(p, v0.w, o_acc[i][3]);
                o_acc[i][4] = fmaf(p, v1.x, o_acc[i][4]);
                o_acc[i][5] = fmaf(p, v1.y, o_acc[i][5]);
                o_acc[i][6] = fmaf(p, v1.z, o_acc[i][6]);
                o_acc[i][7] = fmaf(p, v1.w, o_acc[i][7]);
            }
        }
    }

    // ---- epilogue: O / l ----
#pragma unroll
    for (int i = 0; i < 4; i++) {
        float inv = 1.f / l_i[i];
        float* Orow = O + (size_t)(q0 + ty * 4 + i) * (NH * HD) + h * HD + tx * 8;
        *(float4*)(Orow)     = make_float4(o_acc[i][0] * inv, o_acc[i][1] * inv,
                                           o_acc[i][2] * inv, o_acc[i][3] * inv);
        *(float4*)(Orow + 4) = make_float4(o_acc[i][4] * inv, o_acc[i][5] * inv,
                                           o_acc[i][6] * inv, o_acc[i][7] * inv);
    }
}

// ================= launcher =================
extern "C" void kernel_launch(void* const* d_in, const int* in_sizes, int n_in,
                              void* d_out, int out_size)
{
    const float* X  = (const float*)d_in[0];
    const float* Wq = (const float*)d_in[1];
    const float* Wk = (const float*)d_in[2];
    const float* Wv = (const float*)d_in[3];
    const float* Wo = (const float*)d_in[4];
    float* out = (float*)d_out;

    float *Qp, *Kp, *Vp, *Ap;
    cudaGetSymbolAddress((void**)&Qp, g_Q);
    cudaGetSymbolAddress((void**)&Kp, g_K);
    cudaGetSymbolAddress((void**)&Vp, g_V);
    cudaGetSymbolAddress((void**)&Ap, g_attn);

    dim3 blk(256);

    // QKV projections
    sgemm128x128<<<dim3((NH * HD) / 128, S_LEN / 128), blk>>>(X, Wq, Qp, S_LEN, NH * HD, HID);
    sgemm128x128<<<dim3((NKV * HD) / 128, S_LEN / 128), blk>>>(X, Wk, Kp, S_LEN, NKV * HD, HID);
    sgemm128x128<<<dim3((NKV * HD) / 128, S_LEN / 128), blk>>>(X, Wv, Vp, S_LEN, NKV * HD, HID);

    // RoPE on Q and K (4 pairs per thread)
    int tq = S_LEN * NH * 16;
    int tk = S_LEN * NKV * 16;
    rope_kernel<<<(tq + 255) / 256, 256>>>(Qp, NH);
    rope_kernel<<<(tk + 255) / 256, 256>>>(Kp, NKV);

    // flash attention
    const int smem = (2 * 64 * KSTR + 64 * PSTR) * (int)sizeof(float);  // 84224 B
    cudaFuncSetAttribute(flash_kernel, cudaFuncAttributeMaxDynamicSharedMemorySize, smem);
    flash_kernel<<<dim3(S_LEN / BQ, NH), blk, smem>>>(Qp, Kp, Vp, Ap);

    // output projection
    sgemm128x128<<<dim3(HID / 128, S_LEN / 128), blk>>>(Ap, Wo, out, S_LEN, HID, HID);
}

// round 7
// speedup vs baseline: 1.6926x; 1.5193x over previous
#include <cuda_runtime.h>
#include <math.h>
#include <stdint.h>

#define S_LEN 2048
#define HID   4096
#define NH    32
#define NKV   8
#define HD    128

// -------- scratch (device globals; no allocation allowed) --------
__device__ float g_Q[S_LEN * NH * HD];     // 32 MB
__device__ float g_K[S_LEN * NKV * HD];    // 8 MB
__device__ float g_V[S_LEN * NKV * HD];    // 8 MB
__device__ float g_attn[S_LEN * NH * HD];  // 32 MB

// ---------------- tf32 helpers ----------------
__device__ __forceinline__ float to_tf32(float x) {
    uint32_t u;
    asm("cvt.rna.tf32.f32 %0, %1;" : "=r"(u) : "f"(x));
    return __uint_as_float(u);
}

__device__ __forceinline__ void mma_tf32(float& d0, float& d1, float& d2, float& d3,
                                         uint32_t a0, uint32_t a1, uint32_t a2, uint32_t a3,
                                         uint32_t b0, uint32_t b1) {
    asm volatile(
        "mma.sync.aligned.m16n8k8.row.col.f32.tf32.tf32.f32 "
        "{%0,%1,%2,%3}, {%4,%5,%6,%7}, {%8,%9}, {%0,%1,%2,%3};"
        : "+f"(d0), "+f"(d1), "+f"(d2), "+f"(d3)
        : "r"(a0), "r"(a1), "r"(a2), "r"(a3), "r"(b0), "r"(b1));
}

// ============ TF32 GEMM: C[M,N] = A[M,K] @ B[K,N], row-major ============
// 128x128 block, BK=8, 256 threads (8 warps, 2m x 4n), warp tile 64x32.
// smem pitch 136 floats -> conflict-free frag loads.
#define AST 136
__global__ __launch_bounds__(256, 2)
void sgemm_tf32(const float* __restrict__ A, const float* __restrict__ B,
                float* __restrict__ C, int M, int N, int K)
{
    __shared__ float As[2][8][AST];   // [buf][k][m]
    __shared__ float Bs[2][8][AST];   // [buf][k][n]

    const int tid  = threadIdx.x;
    const int lane = tid & 31;
    const int wid  = tid >> 5;
    const int warp_m = wid & 1;       // 0..1  (64-row tiles)
    const int warp_n = wid >> 1;      // 0..3  (32-col tiles)
    const int bn = blockIdx.x, bm = blockIdx.y;

    const int r = lane >> 2;          // 0..7
    const int c = lane & 3;           // 0..3

    const float* Ab = A + (size_t)bm * 128 * K;
    const float* Bb = B + (size_t)bn * 128;

    const int arow = tid >> 1, acol = (tid & 1) * 4;
    const int brow = tid >> 5, bcol = (tid & 31) * 4;

    float acc[4][4][4];               // [mfrag][nfrag][reg]
#pragma unroll
    for (int f = 0; f < 4; f++)
#pragma unroll
        for (int g = 0; g < 4; g++)
#pragma unroll
            for (int x = 0; x < 4; x++) acc[f][g][x] = 0.f;

    // ---- preload tile 0 ----
    {
        float4 av = *(const float4*)(Ab + (size_t)arow * K + acol);
        float4 bv = *(const float4*)(Bb + (size_t)brow * N + bcol);
        As[0][acol + 0][arow] = to_tf32(av.x);
        As[0][acol + 1][arow] = to_tf32(av.y);
        As[0][acol + 2][arow] = to_tf32(av.z);
        As[0][acol + 3][arow] = to_tf32(av.w);
        float4 bc = make_float4(to_tf32(bv.x), to_tf32(bv.y), to_tf32(bv.z), to_tf32(bv.w));
        *(float4*)&Bs[0][brow][bcol] = bc;
    }
    __syncthreads();

    int buf = 0;
    for (int kt = 8; kt <= K; kt += 8) {
        float4 av, bv;
        const bool more = (kt < K);
        if (more) {
            av = *(const float4*)(Ab + (size_t)arow * K + kt + acol);
            bv = *(const float4*)(Bb + (size_t)(kt + brow) * N + bcol);
        }

        // ---- frag loads + 16 MMAs on current buffer ----
        uint32_t af[4][4], bf[4][2];
#pragma unroll
        for (int f = 0; f < 4; f++) {
            const int mb = warp_m * 64 + f * 16;
            af[f][0] = __float_as_uint(As[buf][c    ][mb + r    ]);
            af[f][1] = __float_as_uint(As[buf][c    ][mb + r + 8]);
            af[f][2] = __float_as_uint(As[buf][c + 4][mb + r    ]);
            af[f][3] = __float_as_uint(As[buf][c + 4][mb + r + 8]);
        }
#pragma unroll
        for (int g = 0; g < 4; g++) {
            const int nb = warp_n * 32 + g * 8;
            bf[g][0] = __float_as_uint(Bs[buf][c    ][nb + r]);
            bf[g][1] = __float_as_uint(Bs[buf][c + 4][nb + r]);
        }
#pragma unroll
        for (int f = 0; f < 4; f++)
#pragma unroll
            for (int g = 0; g < 4; g++)
                mma_tf32(acc[f][g][0], acc[f][g][1], acc[f][g][2], acc[f][g][3],
                         af[f][0], af[f][1], af[f][2], af[f][3],
                         bf[g][0], bf[g][1]);

        if (more) {
            As[buf ^ 1][acol + 0][arow] = to_tf32(av.x);
            As[buf ^ 1][acol + 1][arow] = to_tf32(av.y);
            As[buf ^ 1][acol + 2][arow] = to_tf32(av.z);
            As[buf ^ 1][acol + 3][arow] = to_tf32(av.w);
            float4 bc = make_float4(to_tf32(bv.x), to_tf32(bv.y), to_tf32(bv.z), to_tf32(bv.w));
            *(float4*)&Bs[buf ^ 1][brow][bcol] = bc;
            __syncthreads();
            buf ^= 1;
        }
    }

    // ---- epilogue: float2 stores ----
#pragma unroll
    for (int f = 0; f < 4; f++) {
        const int row0 = bm * 128 + warp_m * 64 + f * 16 + r;
#pragma unroll
        for (int g = 0; g < 4; g++) {
            const int col0 = bn * 128 + warp_n * 32 + g * 8 + 2 * c;
            *(float2*)&C[(size_t)row0 * N + col0]       = make_float2(acc[f][g][0], acc[f][g][1]);
            *(float2*)&C[(size_t)(row0 + 8) * N + col0] = make_float2(acc[f][g][2], acc[f][g][3]);
        }
    }
}

// ================= llama3-smoothed RoPE, in place, fp32, float4 =================
__global__ __launch_bounds__(256)
void rope_kernel(float* __restrict__ x, int nheads)
{
    int idx = blockIdx.x * blockDim.x + threadIdx.x;
    int total = S_LEN * nheads * 16;           // 16 float4-pair groups per head
    if (idx >= total) return;
    int g = idx & 15;
    int h = (idx >> 4) % nheads;
    int s = idx / (16 * nheads);

    const float LOG2_BASE = 18.93156856932417f;   // log2(500000)
    const float TWO_PI    = 6.283185307179586f;

    float* row = x + (size_t)s * nheads * HD + h * HD;
    float4 v1 = *(float4*)&row[g * 4];
    float4 v2 = *(float4*)&row[g * 4 + 64];

    float o1[4], o2[4];
#pragma unroll
    for (int t = 0; t < 4; t++) {
        int i = g * 4 + t;
        float inv_freq = exp2f(-((float)(2 * i) / 128.0f) * LOG2_BASE);
        float wavelen  = TWO_PI / inv_freq;
        float smooth   = (8192.0f / wavelen - 1.0f) * (1.0f / 3.0f);
        smooth = fminf(1.0f, fmaxf(0.0f, smooth));
        float freq = (1.0f - smooth) * (inv_freq * 0.125f) + smooth * inv_freq;

        float c, sn;
        sincosf((float)s * freq, &sn, &c);
        float x1 = (&v1.x)[t], x2 = (&v2.x)[t];
        o1[t] = x1 * c - x2 * sn;
        o2[t] = x2 * c + x1 * sn;
    }
    *(float4*)&row[g * 4]      = make_float4(o1[0], o1[1], o1[2], o1[3]);
    *(float4*)&row[g * 4 + 64] = make_float4(o2[0], o2[1], o2[2], o2[3]);
}

// ================= Flash attention (causal, GQA), fp32 =================
#define BQ 64
#define BKV 64
#define KSTR 132
#define PSTR 65

__global__ __launch_bounds__(256, 1)
void flash_kernel(const float* __restrict__ Q, const float* __restrict__ K,
                  const float* __restrict__ V, float* __restrict__ O)
{
    extern __shared__ float sm[];
    float* Qs  = sm;                       // [64][132]
    float* KVs = sm + 64 * KSTR;           // [64][132]
    float* Ps  = sm + 2 * 64 * KSTR;       // [64][65]

    const int qt  = gridDim.x - 1 - blockIdx.x;
    const int h   = blockIdx.y;
    const int kvh = h >> 2;
    const int tid = threadIdx.x;
    const int tx = tid & 15, ty = tid >> 4;
    const int q0 = qt * BQ;
    const float scale = 0.08838834764831845f;

    for (int t = tid; t < 64 * 32; t += 256) {
        int r = t >> 5, c4 = (t & 31) << 2;
        *(float4*)&Qs[r * KSTR + c4] =
            *(const float4*)&Q[(size_t)(q0 + r) * (NH * HD) + h * HD + c4];
    }

    float m_i[4], l_i[4], o_acc[4][8];
#pragma unroll
    for (int i = 0; i < 4; i++) {
        m_i[i] = -INFINITY;
        l_i[i] = 0.f;
#pragma unroll
        for (int j = 0; j < 8; j++) o_acc[i][j] = 0.f;
    }

    for (int j = 0; j <= qt; j++) {
        const int k0 = j * BKV;
        __syncthreads();
        for (int t = tid; t < 64 * 32; t += 256) {
            int r = t >> 5, c4 = (t & 31) << 2;
            *(float4*)&KVs[r * KSTR + c4] =
                *(const float4*)&K[(size_t)(k0 + r) * (NKV * HD) + kvh * HD + c4];
        }
        __syncthreads();

        float sacc[4][4];
#pragma unroll
        for (int i = 0; i < 4; i++)
#pragma unroll
            for (int jj = 0; jj < 4; jj++) sacc[i][jj] = 0.f;

#pragma unroll 8
        for (int d = 0; d < HD; d += 4) {
            float4 qa[4], kb[4];
#pragma unroll
            for (int i = 0; i < 4; i++)
                qa[i] = *(const float4*)&Qs[(ty * 4 + i) * KSTR + d];
#pragma unroll
            for (int i = 0; i < 4; i++)
                kb[i] = *(const float4*)&KVs[(tx * 4 + i) * KSTR + d];
#pragma unroll
            for (int i = 0; i < 4; i++)
#pragma unroll
                for (int jj = 0; jj < 4; jj++) {
                    sacc[i][jj] = fmaf(qa[i].x, kb[jj].x, sacc[i][jj]);
                    sacc[i][jj] = fmaf(qa[i].y, kb[jj].y, sacc[i][jj]);
                    sacc[i][jj] = fmaf(qa[i].z, kb[jj].z, sacc[i][jj]);
                    sacc[i][jj] = fmaf(qa[i].w, kb[jj].w, sacc[i][jj]);
                }
        }

        const bool diag = (j == qt);
#pragma unroll
        for (int i = 0; i < 4; i++)
#pragma unroll
            for (int jj = 0; jj < 4; jj++) {
                float v = sacc[i][jj] * scale;
                if (diag && (k0 + tx * 4 + jj) > (q0 + ty * 4 + i)) v = -INFINITY;
                sacc[i][jj] = v;
            }

        float mt[4], mn[4], alpha[4], rs[4];
#pragma unroll
        for (int i = 0; i < 4; i++) {
            mt[i] = fmaxf(fmaxf(sacc[i][0], sacc[i][1]), fmaxf(sacc[i][2], sacc[i][3]));
#pragma unroll
            for (int off = 8; off >= 1; off >>= 1)
                mt[i] = fmaxf(mt[i], __shfl_xor_sync(0xffffffffu, mt[i], off, 16));
            mn[i]    = fmaxf(m_i[i], mt[i]);
            alpha[i] = expf(m_i[i] - mn[i]);
            float lsum = 0.f;
#pragma unroll
            for (int jj = 0; jj < 4; jj++) {
                float p = expf(sacc[i][jj] - mn[i]);
                sacc[i][jj] = p;
                lsum += p;
            }
#pragma unroll
            for (int off = 8; off >= 1; off >>= 1)
                lsum += __shfl_xor_sync(0xffffffffu, lsum, off, 16);
            rs[i] = lsum;
        }
#pragma unroll
        for (int i = 0; i < 4; i++) {
            l_i[i] = l_i[i] * alpha[i] + rs[i];
            m_i[i] = mn[i];
#pragma unroll
            for (int jj = 0; jj < 8; jj++) o_acc[i][jj] *= alpha[i];
#pragma unroll
            for (int jj = 0; jj < 4; jj++)
                Ps[(ty * 4 + i) * PSTR + tx * 4 + jj] = sacc[i][jj];
        }
        __syncthreads();

        for (int t = tid; t < 64 * 32; t += 256) {
            int r = t >> 5, c4 = (t & 31) << 2;
            *(float4*)&KVs[r * KSTR + c4] =
                *(const float4*)&V[(size_t)(k0 + r) * (NKV * HD) + kvh * HD + c4];
        }
        __syncthreads();

#pragma unroll 4
        for (int c = 0; c < BKV; c++) {
            float4 v0 = *(const float4*)&KVs[c * KSTR + tx * 8];
            float4 v1 = *(const float4*)&KVs[c * KSTR + tx * 8 + 4];
#pragma unroll
            for (int i = 0; i < 4; i++) {
                float p = Ps[(ty * 4 + i) * PSTR + c];
                o_acc[i][0] = fmaf(p, v0.x, o_acc[i][0]);
                o_acc[i][1] = fmaf(p, v0.y, o_acc[i][1]);
                o_acc[i][2] = fmaf(p, v0.z, o_acc[i][2]);
                o_acc[i][3] = fmaf(p, v0.w, o_acc[i][3]);
                o_acc[i][4] = fmaf(p, v1.x, o_acc[i][4]);
                o_acc[i][5] = fmaf(p, v1.y, o_acc[i][5]);
                o_acc[i][6] = fmaf(p, v1.z, o_acc[i][6]);
                o_acc[i][7] = fmaf(p, v1.w, o_acc[i][7]);
            }
        }
    }

#pragma unroll
    for (int i = 0; i < 4; i++) {
        float inv = 1.f / l_i[i];
        float* Orow = O + (size_t)(q0 + ty * 4 + i) * (NH * HD) + h * HD + tx * 8;
        *(float4*)(Orow)     = make_float4(o_acc[i][0] * inv, o_acc[i][1] * inv,
                                           o_acc[i][2] * inv, o_acc[i][3] * inv);
        *(float4*)(Orow + 4) = make_float4(o_acc[i][4] * inv, o_acc[i][5] * inv,
                                           o_acc[i][6] * inv, o_acc[i][7] * inv);
    }
}

// ================= launcher =================
extern "C" void kernel_launch(void* const* d_in, const int* in_sizes, int n_in,
                              void* d_out, int out_size)
{
    const float* X  = (const float*)d_in[0];
    const float* Wq = (const float*)d_in[1];
    const float* Wk = (const float*)d_in[2];
    const float* Wv = (const float*)d_in[3];
    const float* Wo = (const float*)d_in[4];
    float* out = (float*)d_out;

    float *Qp, *Kp, *Vp, *Ap;
    cudaGetSymbolAddress((void**)&Qp, g_Q);
    cudaGetSymbolAddress((void**)&Kp, g_K);
    cudaGetSymbolAddress((void**)&Vp, g_V);
    cudaGetSymbolAddress((void**)&Ap, g_attn);

    dim3 blk(256);

    // QKV projections (tf32 tensor cores)
    sgemm_tf32<<<dim3((NH * HD) / 128, S_LEN / 128), blk>>>(X, Wq, Qp, S_LEN, NH * HD, HID);
    sgemm_tf32<<<dim3((NKV * HD) / 128, S_LEN / 128), blk>>>(X, Wk, Kp, S_LEN, NKV * HD, HID);
    sgemm_tf32<<<dim3((NKV * HD) / 128, S_LEN / 128), blk>>>(X, Wv, Vp, S_LEN, NKV * HD, HID);

    // RoPE on Q and K
    int tq = S_LEN * NH * 16;
    int tk = S_LEN * NKV * 16;
    rope_kernel<<<(tq + 255) / 256, 256>>>(Qp, NH);
    rope_kernel<<<(tk + 255) / 256, 256>>>(Kp, NKV);

    // flash attention (fp32)
    const int smem = (2 * 64 * KSTR + 64 * PSTR) * (int)sizeof(float);  // 84224 B
    cudaFuncSetAttribute(flash_kernel, cudaFuncAttributeMaxDynamicSharedMemorySize, smem);
    flash_kernel<<<dim3(S_LEN / BQ, NH), blk, smem>>>(Qp, Kp, Vp, Ap);

    // output projection (tf32 tensor cores)
    sgemm_tf32<<<dim3(HID / 128, S_LEN / 128), blk>>>(Ap, Wo, out, S_LEN, HID, HID);
}

// round 8
// speedup vs baseline: 1.9800x; 1.1698x over previous
#include <cuda_runtime.h>
#include <math.h>
#include <stdint.h>

#define S_LEN 2048
#define HID   4096
#define NH    32
#define NKV   8
#define HD    128

// -------- scratch (device globals; no allocation allowed) --------
__device__ float g_Q[S_LEN * NH * HD];     // 32 MB
__device__ float g_K[S_LEN * NKV * HD];    // 8 MB
__device__ float g_V[S_LEN * NKV * HD];    // 8 MB
__device__ float g_attn[S_LEN * NH * HD];  // 32 MB

// ---------------- tf32 helpers ----------------
__device__ __forceinline__ uint32_t frag_tf32(float x) {
    uint32_t u;
    asm("cvt.rna.tf32.f32 %0, %1;" : "=r"(u) : "f"(x));
    return u;
}

__device__ __forceinline__ void mma_tf32(float& d0, float& d1, float& d2, float& d3,
                                         uint32_t a0, uint32_t a1, uint32_t a2, uint32_t a3,
                                         uint32_t b0, uint32_t b1) {
    asm volatile(
        "mma.sync.aligned.m16n8k8.row.col.f32.tf32.tf32.f32 "
        "{%0,%1,%2,%3}, {%4,%5,%6,%7}, {%8,%9}, {%0,%1,%2,%3};"
        : "+f"(d0), "+f"(d1), "+f"(d2), "+f"(d3)
        : "r"(a0), "r"(a1), "r"(a2), "r"(a3), "r"(b0), "r"(b1));
}

__device__ __forceinline__ void cp_async16(uint32_t smem_addr, const void* gptr) {
    asm volatile("cp.async.ca.shared.global [%0], [%1], 16;\n"
                 :: "r"(smem_addr), "l"(gptr));
}
__device__ __forceinline__ void cp_commit() {
    asm volatile("cp.async.commit_group;\n" ::: "memory");
}
template <int N>
__device__ __forceinline__ void cp_wait() {
    asm volatile("cp.async.wait_group %0;\n" :: "n"(N) : "memory");
}

// ============ TF32 GEMM: C[M,N] = A[M,K] @ B[K,N], row-major ============
// 128x128 block, BK=16, 256 threads (8 warps, 2m x 4n), warp tile 64x32.
// 3-stage cp.async pipeline; A smem [m][k] pitch 20, B smem [k][n] pitch 136.
#define APITCH 20
#define BPITCH 136
#define A_ELEMS (128 * APITCH)                 // 2560 floats
#define B_ELEMS (16 * BPITCH)                  // 2176 floats
#define STAGE_ELEMS (A_ELEMS + B_ELEMS)        // 4736 floats
#define NSTAGE 3

__global__ __launch_bounds__(256, 2)
void sgemm_tf32(const float* __restrict__ A, const float* __restrict__ B,
                float* __restrict__ C, int M, int N, int K)
{
    extern __shared__ float smem[];

    const int tid  = threadIdx.x;
    const int lane = tid & 31;
    const int wid  = tid >> 5;
    const int warp_m = wid & 1;       // 0..1  (64-row tiles)
    const int warp_n = wid >> 1;      // 0..3  (32-col tiles)
    const int bn = blockIdx.x, bm = blockIdx.y;

    const int r = lane >> 2;          // 0..7
    const int c = lane & 3;           // 0..3

    // cp.async assignments
    const int am  = tid >> 1;                 // A row within tile (0..127)
    const int ak8 = (tid & 1) * 8;            // A col chunk (0 or 8)
    const int bk  = tid >> 4;                 // B row within tile (0..15)
    const int bn0 = (tid & 15) * 8;           // B col chunk

    const float* Ag = A + (size_t)(bm * 128 + am) * K + ak8;
    const float* Bg = B + (size_t)bk * N + bn * 128 + bn0;

    uint32_t smem_base;
    asm("{ .reg .u64 t; cvta.to.shared.u64 t, %1; cvt.u32.u64 %0, t; }"
        : "=r"(smem_base) : "l"(smem));

    float acc[4][4][4];
#pragma unroll
    for (int f = 0; f < 4; f++)
#pragma unroll
        for (int g = 0; g < 4; g++)
#pragma unroll
            for (int x = 0; x < 4; x++) acc[f][g][x] = 0.f;

    const int ntiles = K >> 4;

    // ---- issue prefetch for tiles 0 and 1 ----
#pragma unroll
    for (int pf = 0; pf < 2; pf++) {
        uint32_t sa = smem_base + (pf * STAGE_ELEMS + am * APITCH + ak8) * 4;
        cp_async16(sa,     Ag + (size_t)pf * 16);
        cp_async16(sa + 16, Ag + (size_t)pf * 16 + 4);
        uint32_t sb = smem_base + (pf * STAGE_ELEMS + A_ELEMS + bk * BPITCH + bn0) * 4;
        cp_async16(sb,     Bg + (size_t)pf * 16 * N);
        cp_async16(sb + 16, Bg + (size_t)pf * 16 * N + 4);
        cp_commit();
    }

    for (int kt = 0; kt < ntiles; kt++) {
        cp_wait<1>();
        __syncthreads();

        // issue loads for tile kt+2
        if (kt + 2 < ntiles) {
            int st = (kt + 2) % NSTAGE;
            uint32_t sa = smem_base + (st * STAGE_ELEMS + am * APITCH + ak8) * 4;
            cp_async16(sa,      Ag + (size_t)(kt + 2) * 16);
            cp_async16(sa + 16, Ag + (size_t)(kt + 2) * 16 + 4);
            uint32_t sb = smem_base + (st * STAGE_ELEMS + A_ELEMS + bk * BPITCH + bn0) * 4;
            cp_async16(sb,      Bg + (size_t)(kt + 2) * 16 * N);
            cp_async16(sb + 16, Bg + (size_t)(kt + 2) * 16 * N + 4);
        }
        cp_commit();

        const float* As = smem + (kt % NSTAGE) * STAGE_ELEMS;
        const float* Bs = As + A_ELEMS;

        // two 8-k steps
#pragma unroll
        for (int s = 0; s < 2; s++) {
            const int k0 = s * 8;
            uint32_t af[4][4], bf[4][2];
#pragma unroll
            for (int f = 0; f < 4; f++) {
                const int mb = warp_m * 64 + f * 16;
                af[f][0] = frag_tf32(As[(mb + r    ) * APITCH + k0 + c    ]);
                af[f][1] = frag_tf32(As[(mb + r + 8) * APITCH + k0 + c    ]);
                af[f][2] = frag_tf32(As[(mb + r    ) * APITCH + k0 + c + 4]);
                af[f][3] = frag_tf32(As[(mb + r + 8) * APITCH + k0 + c + 4]);
            }
#pragma unroll
            for (int g = 0; g < 4; g++) {
                const int nb = warp_n * 32 + g * 8;
                bf[g][0] = frag_tf32(Bs[(k0 + c    ) * BPITCH + nb + r]);
                bf[g][1] = frag_tf32(Bs[(k0 + c + 4) * BPITCH + nb + r]);
            }
#pragma unroll
            for (int f = 0; f < 4; f++)
#pragma unroll
                for (int g = 0; g < 4; g++)
                    mma_tf32(acc[f][g][0], acc[f][g][1], acc[f][g][2], acc[f][g][3],
                             af[f][0], af[f][1], af[f][2], af[f][3],
                             bf[g][0], bf[g][1]);
        }
    }

    // ---- epilogue: float2 stores ----
#pragma unroll
    for (int f = 0; f < 4; f++) {
        const int row0 = bm * 128 + warp_m * 64 + f * 16 + r;
#pragma unroll
        for (int g = 0; g < 4; g++) {
            const int col0 = bn * 128 + warp_n * 32 + g * 8 + 2 * c;
            *(float2*)&C[(size_t)row0 * N + col0]       = make_float2(acc[f][g][0], acc[f][g][1]);
            *(float2*)&C[(size_t)(row0 + 8) * N + col0] = make_float2(acc[f][g][2], acc[f][g][3]);
        }
    }
}

// ================= llama3-smoothed RoPE, in place, fp32, float4 =================
__global__ __launch_bounds__(256)
void rope_kernel(float* __restrict__ x, int nheads)
{
    int idx = blockIdx.x * blockDim.x + threadIdx.x;
    int total = S_LEN * nheads * 16;           // 16 float4-pair groups per head
    if (idx >= total) return;
    int g = idx & 15;
    int h = (idx >> 4) % nheads;
    int s = idx / (16 * nheads);

    const float LOG2_BASE = 18.93156856932417f;   // log2(500000)
    const float TWO_PI    = 6.283185307179586f;

    float* row = x + (size_t)s * nheads * HD + h * HD;
    float4 v1 = *(float4*)&row[g * 4];
    float4 v2 = *(float4*)&row[g * 4 + 64];

    float o1[4], o2[4];
#pragma unroll
    for (int t = 0; t < 4; t++) {
        int i = g * 4 + t;
        float inv_freq = exp2f(-((float)(2 * i) / 128.0f) * LOG2_BASE);
        float wavelen  = TWO_PI / inv_freq;
        float smooth   = (8192.0f / wavelen - 1.0f) * (1.0f / 3.0f);
        smooth = fminf(1.0f, fmaxf(0.0f, smooth));
        float freq = (1.0f - smooth) * (inv_freq * 0.125f) + smooth * inv_freq;

        float c, sn;
        sincosf((float)s * freq, &sn, &c);
        float x1 = (&v1.x)[t], x2 = (&v2.x)[t];
        o1[t] = x1 * c - x2 * sn;
        o2[t] = x2 * c + x1 * sn;
    }
    *(float4*)&row[g * 4]      = make_float4(o1[0], o1[1], o1[2], o1[3]);
    *(float4*)&row[g * 4 + 64] = make_float4(o2[0], o2[1], o2[2], o2[3]);
}

// ================= Flash attention (causal, GQA), fp32 =================
#define BQ 64
#define BKV 64
#define KSTR 132
#define PSTR 65

__global__ __launch_bounds__(256, 1)
void flash_kernel(const float* __restrict__ Q, const float* __restrict__ K,
                  const float* __restrict__ V, float* __restrict__ O)
{
    extern __shared__ float sm[];
    float* Qs  = sm;                       // [64][132]
    float* KVs = sm + 64 * KSTR;           // [64][132]
    float* Ps  = sm + 2 * 64 * KSTR;       // [64][65]

    const int qt  = gridDim.x - 1 - blockIdx.x;
    const int h   = blockIdx.y;
    const int kvh = h >> 2;
    const int tid = threadIdx.x;
    const int tx = tid & 15, ty = tid >> 4;
    const int q0 = qt * BQ;
    const float scale = 0.08838834764831845f;

    for (int t = tid; t < 64 * 32; t += 256) {
        int r = t >> 5, c4 = (t & 31) << 2;
        *(float4*)&Qs[r * KSTR + c4] =
            *(const float4*)&Q[(size_t)(q0 + r) * (NH * HD) + h * HD + c4];
    }

    float m_i[4], l_i[4], o_acc[4][8];
#pragma unroll
    for (int i = 0; i < 4; i++) {
        m_i[i] = -INFINITY;
        l_i[i] = 0.f;
#pragma unroll
        for (int j = 0; j < 8; j++) o_acc[i][j] = 0.f;
    }

    for (int j = 0; j <= qt; j++) {
        const int k0 = j * BKV;
        __syncthreads();
        for (int t = tid; t < 64 * 32; t += 256) {
            int r = t >> 5, c4 = (t & 31) << 2;
            *(float4*)&KVs[r * KSTR + c4] =
                *(const float4*)&K[(size_t)(k0 + r) * (NKV * HD) + kvh * HD + c4];
        }
        __syncthreads();

        float sacc[4][4];
#pragma unroll
        for (int i = 0; i < 4; i++)
#pragma unroll
            for (int jj = 0; jj < 4; jj++) sacc[i][jj] = 0.f;

#pragma unroll 8
        for (int d = 0; d < HD; d += 4) {
            float4 qa[4], kb[4];
#pragma unroll
            for (int i = 0; i < 4; i++)
                qa[i] = *(const float4*)&Qs[(ty * 4 + i) * KSTR + d];
#pragma unroll
            for (int i = 0; i < 4; i++)
                kb[i] = *(const float4*)&KVs[(tx * 4 + i) * KSTR + d];
#pragma unroll
            for (int i = 0; i < 4; i++)
#pragma unroll
                for (int jj = 0; jj < 4; jj++) {
                    sacc[i][jj] = fmaf(qa[i].x, kb[jj].x, sacc[i][jj]);
                    sacc[i][jj] = fmaf(qa[i].y, kb[jj].y, sacc[i][jj]);
                    sacc[i][jj] = fmaf(qa[i].z, kb[jj].z, sacc[i][jj]);
                    sacc[i][jj] = fmaf(qa[i].w, kb[jj].w, sacc[i][jj]);
                }
        }

        const bool diag = (j == qt);
#pragma unroll
        for (int i = 0; i < 4; i++)
#pragma unroll
            for (int jj = 0; jj < 4; jj++) {
                float v = sacc[i][jj] * scale;
                if (diag && (k0 + tx * 4 + jj) > (q0 + ty * 4 + i)) v = -INFINITY;
                sacc[i][jj] = v;
            }

        float mt[4], mn[4], alpha[4], rs[4];
#pragma unroll
        for (int i = 0; i < 4; i++) {
            mt[i] = fmaxf(fmaxf(sacc[i][0], sacc[i][1]), fmaxf(sacc[i][2], sacc[i][3]));
#pragma unroll
            for (int off = 8; off >= 1; off >>= 1)
                mt[i] = fmaxf(mt[i], __shfl_xor_sync(0xffffffffu, mt[i], off, 16));
            mn[i]    = fmaxf(m_i[i], mt[i]);
            alpha[i] = expf(m_i[i] - mn[i]);
            float lsum = 0.f;
#pragma unroll
            for (int jj = 0; jj < 4; jj++) {
                float p = expf(sacc[i][jj] - mn[i]);
                sacc[i][jj] = p;
                lsum += p;
            }
#pragma unroll
            for (int off = 8; off >= 1; off >>= 1)
                lsum += __shfl_xor_sync(0xffffffffu, lsum, off, 16);
            rs[i] = lsum;
        }
#pragma unroll
        for (int i = 0; i < 4; i++) {
            l_i[i] = l_i[i] * alpha[i] + rs[i];
            m_i[i] = mn[i];
#pragma unroll
            for (int jj = 0; jj < 8; jj++) o_acc[i][jj] *= alpha[i];
#pragma unroll
            for (int jj = 0; jj < 4; jj++)
                Ps[(ty * 4 + i) * PSTR + tx * 4 + jj] = sacc[i][jj];
        }
        __syncthreads();

        for (int t = tid; t < 64 * 32; t += 256) {
            int r = t >> 5, c4 = (t & 31) << 2;
            *(float4*)&KVs[r * KSTR + c4] =
                *(const float4*)&V[(size_t)(k0 + r) * (NKV * HD) + kvh * HD + c4];
        }
        __syncthreads();

#pragma unroll 4
        for (int c = 0; c < BKV; c++) {
            float4 v0 = *(const float4*)&KVs[c * KSTR + tx * 8];
            float4 v1 = *(const float4*)&KVs[c * KSTR + tx * 8 + 4];
#pragma unroll
            for (int i = 0; i < 4; i++) {
                float p = Ps[(ty * 4 + i) * PSTR + c];
                o_acc[i][0] = fmaf(p, v0.x, o_acc[i][0]);
                o_acc[i][1] = fmaf(p, v0.y, o_acc[i][1]);
                o_acc[i][2] = fmaf(p, v0.z, o_acc[i][2]);
                o_acc[i][3] = fmaf(p, v0.w, o_acc[i][3]);
                o_acc[i][4] = fmaf(p, v1.x, o_acc[i][4]);
                o_acc[i][5] = fmaf(p, v1.y, o_acc[i][5]);
                o_acc[i][6] = fmaf(p, v1.z, o_acc[i][6]);
                o_acc[i][7] = fmaf(p, v1.w, o_acc[i][7]);
            }
        }
    }

#pragma unroll
    for (int i = 0; i < 4; i++) {
        float inv = 1.f / l_i[i];
        float* Orow = O + (size_t)(q0 + ty * 4 + i) * (NH * HD) + h * HD + tx * 8;
        *(float4*)(Orow)     = make_float4(o_acc[i][0] * inv, o_acc[i][1] * inv,
                                           o_acc[i][2] * inv, o_acc[i][3] * inv);
        *(float4*)(Orow + 4) = make_float4(o_acc[i][4] * inv, o_acc[i][5] * inv,
                                           o_acc[i][6] * inv, o_acc[i][7] * inv);
    }
}

// ================= launcher =================
extern "C" void kernel_launch(void* const* d_in, const int* in_sizes, int n_in,
                              void* d_out, int out_size)
{
    const float* X  = (const float*)d_in[0];
    const float* Wq = (const float*)d_in[1];
    const float* Wk = (const float*)d_in[2];
    const float* Wv = (const float*)d_in[3];
    const float* Wo = (const float*)d_in[4];
    float* out = (float*)d_out;

    float *Qp, *Kp, *Vp, *Ap;
    cudaGetSymbolAddress((void**)&Qp, g_Q);
    cudaGetSymbolAddress((void**)&Kp, g_K);
    cudaGetSymbolAddress((void**)&Vp, g_V);
    cudaGetSymbolAddress((void**)&Ap, g_attn);

    dim3 blk(256);
    const int gemm_smem = NSTAGE * STAGE_ELEMS * (int)sizeof(float);  // 56832 B
    cudaFuncSetAttribute(sgemm_tf32, cudaFuncAttributeMaxDynamicSharedMemorySize, gemm_smem);

    // QKV projections (tf32 tensor cores, cp.async pipeline)
    sgemm_tf32<<<dim3((NH * HD) / 128, S_LEN / 128), blk, gemm_smem>>>(X, Wq, Qp, S_LEN, NH * HD, HID);
    sgemm_tf32<<<dim3((NKV * HD) / 128, S_LEN / 128), blk, gemm_smem>>>(X, Wk, Kp, S_LEN, NKV * HD, HID);
    sgemm_tf32<<<dim3((NKV * HD) / 128, S_LEN / 128), blk, gemm_smem>>>(X, Wv, Vp, S_LEN, NKV * HD, HID);

    // RoPE on Q and K
    int tq = S_LEN * NH * 16;
    int tk = S_LEN * NKV * 16;
    rope_kernel<<<(tq + 255) / 256, 256>>>(Qp, NH);
    rope_kernel<<<(tk + 255) / 256, 256>>>(Kp, NKV);

    // flash attention (fp32)
    const int smem = (2 * 64 * KSTR + 64 * PSTR) * (int)sizeof(float);  // 84224 B
    cudaFuncSetAttribute(flash_kernel, cudaFuncAttributeMaxDynamicSharedMemorySize, smem);
    flash_kernel<<<dim3(S_LEN / BQ, NH), blk, smem>>>(Qp, Kp, Vp, Ap);

    // output projection (tf32 tensor cores)
    sgemm_tf32<<<dim3(HID / 128, S_LEN / 128), blk, gemm_smem>>>(Ap, Wo, out, S_LEN, HID, HID);
}

// round 10
// speedup vs baseline: 2.1150x; 1.0682x over previous
#include <cuda_runtime.h>
#include <math.h>
#include <stdint.h>

#define S_LEN 2048
#define HID   4096
#define NH    32
#define NKV   8
#define HD    128

// -------- scratch (device globals; no allocation allowed) --------
__device__ float g_Q[S_LEN * NH * HD];     // 32 MB
__device__ float g_K[S_LEN * NKV * HD];    // 8 MB
__device__ float g_V[S_LEN * NKV * HD];    // 8 MB
__device__ float g_attn[S_LEN * NH * HD];  // 32 MB

// ---------------- tf32 helpers ----------------
__device__ __forceinline__ uint32_t frag_tf32(float x) {
    uint32_t u;
    asm("cvt.rna.tf32.f32 %0, %1;" : "=r"(u) : "f"(x));
    return u;
}

__device__ __forceinline__ void mma_tf32(float& d0, float& d1, float& d2, float& d3,
                                         uint32_t a0, uint32_t a1, uint32_t a2, uint32_t a3,
                                         uint32_t b0, uint32_t b1) {
    asm volatile(
        "mma.sync.aligned.m16n8k8.row.col.f32.tf32.tf32.f32 "
        "{%0,%1,%2,%3}, {%4,%5,%6,%7}, {%8,%9}, {%0,%1,%2,%3};"
        : "+f"(d0), "+f"(d1), "+f"(d2), "+f"(d3)
        : "r"(a0), "r"(a1), "r"(a2), "r"(a3), "r"(b0), "r"(b1));
}

__device__ __forceinline__ void cp_async16(uint32_t smem_addr, const void* gptr) {
    asm volatile("cp.async.cg.shared.global [%0], [%1], 16;\n"
                 :: "r"(smem_addr), "l"(gptr));
}
__device__ __forceinline__ void cp_commit() {
    asm volatile("cp.async.commit_group;\n" ::: "memory");
}
template <int N>
__device__ __forceinline__ void cp_wait() {
    asm volatile("cp.async.wait_group %0;\n" :: "n"(N) : "memory");
}

// ============ TF32 GEMM core (shared by generic + fused-QKV kernels) ============
// 128x128 block, BK=16, 256 threads (8 warps, 2m x 4n), warp tile 64x32.
// 3-stage cp.async pipeline; A smem [m][k] pitch 20, B smem [k][n] pitch 136.
#define APITCH 20
#define BPITCH 136
#define A_ELEMS (128 * APITCH)                 // 2560 floats
#define B_ELEMS (16 * BPITCH)                  // 2176 floats
#define STAGE_ELEMS (A_ELEMS + B_ELEMS)        // 4736 floats
#define NSTAGE 3

// A: row-major [M x K] (base already offset to this CTA's 128-row stripe)
// B: row-major [K x NB] (base already offset to this CTA's 128-col stripe)
// C: row-major, stride NC (base already offset to this CTA's 128x128 tile)
__device__ __forceinline__ void gemm_tile_tf32(
    const float* __restrict__ Ag0, int K,
    const float* __restrict__ Bg0, int NB,
    float* __restrict__ Ct, int NC, float* smem)
{
    const int tid  = threadIdx.x;
    const int lane = tid & 31;
    const int wid  = tid >> 5;
    const int warp_m = wid & 1;
    const int warp_n = wid >> 1;
    const int r = lane >> 2;
    const int c = lane & 3;

    const int am  = tid >> 1;
    const int ak8 = (tid & 1) * 8;
    const int bk  = tid >> 4;
    const int bn0 = (tid & 15) * 8;

    const float* Ag = Ag0 + (size_t)am * K + ak8;
    const float* Bg = Bg0 + (size_t)bk * NB + bn0;

    uint32_t smem_base;
    asm("{ .reg .u64 t; cvta.to.shared.u64 t, %1; cvt.u32.u64 %0, t; }"
        : "=r"(smem_base) : "l"(smem));

    float acc[4][4][4];
#pragma unroll
    for (int f = 0; f < 4; f++)
#pragma unroll
        for (int g = 0; g < 4; g++)
#pragma unroll
            for (int x = 0; x < 4; x++) acc[f][g][x] = 0.f;

    const int ntiles = K >> 4;

#pragma unroll
    for (int pf = 0; pf < 2; pf++) {
        uint32_t sa = smem_base + (pf * STAGE_ELEMS + am * APITCH + ak8) * 4;
        cp_async16(sa,      Ag + (size_t)pf * 16);
        cp_async16(sa + 16, Ag + (size_t)pf * 16 + 4);
        uint32_t sb = smem_base + (pf * STAGE_ELEMS + A_ELEMS + bk * BPITCH + bn0) * 4;
        cp_async16(sb,      Bg + (size_t)pf * 16 * NB);
        cp_async16(sb + 16, Bg + (size_t)pf * 16 * NB + 4);
        cp_commit();
    }

    for (int kt = 0; kt < ntiles; kt++) {
        cp_wait<1>();
        __syncthreads();

        if (kt + 2 < ntiles) {
            int st = (kt + 2) % NSTAGE;
            uint32_t sa = smem_base + (st * STAGE_ELEMS + am * APITCH + ak8) * 4;
            cp_async16(sa,      Ag + (size_t)(kt + 2) * 16);
            cp_async16(sa + 16, Ag + (size_t)(kt + 2) * 16 + 4);
            uint32_t sb = smem_base + (st * STAGE_ELEMS + A_ELEMS + bk * BPITCH + bn0) * 4;
            cp_async16(sb,      Bg + (size_t)(kt + 2) * 16 * NB);
            cp_async16(sb + 16, Bg + (size_t)(kt + 2) * 16 * NB + 4);
        }
        cp_commit();

        const float* As = smem + (kt % NSTAGE) * STAGE_ELEMS;
        const float* Bs = As + A_ELEMS;

#pragma unroll
        for (int s = 0; s < 2; s++) {
            const int k0 = s * 8;
            uint32_t af[4][4], bf[4][2];
#pragma unroll
            for (int f = 0; f < 4; f++) {
                const int mb = warp_m * 64 + f * 16;
                af[f][0] = frag_tf32(As[(mb + r    ) * APITCH + k0 + c    ]);
                af[f][1] = frag_tf32(As[(mb + r + 8) * APITCH + k0 + c    ]);
                af[f][2] = frag_tf32(As[(mb + r    ) * APITCH + k0 + c + 4]);
                af[f][3] = frag_tf32(As[(mb + r + 8) * APITCH + k0 + c + 4]);
            }
#pragma unroll
            for (int g = 0; g < 4; g++) {
                const int nb = warp_n * 32 + g * 8;
                bf[g][0] = frag_tf32(Bs[(k0 + c    ) * BPITCH + nb + r]);
                bf[g][1] = frag_tf32(Bs[(k0 + c + 4) * BPITCH + nb + r]);
            }
#pragma unroll
            for (int f = 0; f < 4; f++)
#pragma unroll
                for (int g = 0; g < 4; g++)
                    mma_tf32(acc[f][g][0], acc[f][g][1], acc[f][g][2], acc[f][g][3],
                             af[f][0], af[f][1], af[f][2], af[f][3],
                             bf[g][0], bf[g][1]);
        }
    }

#pragma unroll
    for (int f = 0; f < 4; f++) {
        const int row0 = warp_m * 64 + f * 16 + r;
#pragma unroll
        for (int g = 0; g < 4; g++) {
            const int col0 = warp_n * 32 + g * 8 + 2 * c;
            *(float2*)&Ct[(size_t)row0 * NC + col0]       = make_float2(acc[f][g][0], acc[f][g][1]);
            *(float2*)&Ct[(size_t)(row0 + 8) * NC + col0] = make_float2(acc[f][g][2], acc[f][g][3]);
        }
    }
}

// Generic GEMM (used for Wo)
__global__ __launch_bounds__(256, 2)
void sgemm_tf32(const float* __restrict__ A, const float* __restrict__ B,
                float* __restrict__ C, int M, int N, int K)
{
    extern __shared__ float smem[];
    const int bn = blockIdx.x, bm = blockIdx.y;
    gemm_tile_tf32(A + (size_t)bm * 128 * K, K,
                   B + (size_t)bn * 128, N,
                   C + (size_t)bm * 128 * N + (size_t)bn * 128, N, smem);
}

// Fused QKV projection: one launch covers Wq (bn 0..31), Wk (32..39), Wv (40..47)
__global__ __launch_bounds__(256, 2)
void sgemm_tf32_qkv(const float* __restrict__ X,
                    const float* __restrict__ Wq, const float* __restrict__ Wk,
                    const float* __restrict__ Wv,
                    float* __restrict__ Qo, float* __restrict__ Ko,
                    float* __restrict__ Vo)
{
    extern __shared__ float smem[];
    const int bn = blockIdx.x, bm = blockIdx.y;

    const float* Bb;
    float* Cb;
    int Nw, bnl;
    if (bn < 32)      { Bb = Wq; Cb = Qo; Nw = NH * HD;  bnl = bn; }
    else if (bn < 40) { Bb = Wk; Cb = Ko; Nw = NKV * HD; bnl = bn - 32; }
    else              { Bb = Wv; Cb = Vo; Nw = NKV * HD; bnl = bn - 40; }

    gemm_tile_tf32(X + (size_t)bm * 128 * HID, HID,
                   Bb + (size_t)bnl * 128, Nw,
                   Cb + (size_t)bm * 128 * Nw + (size_t)bnl * 128, Nw, smem);
}

// ================= llama3-smoothed RoPE, in place, fp32, float4 =================
__global__ __launch_bounds__(256)
void rope_kernel(float* __restrict__ x, int nheads)
{
    int idx = blockIdx.x * blockDim.x + threadIdx.x;
    int total = S_LEN * nheads * 16;
    if (idx >= total) return;
    int g = idx & 15;
    int h = (idx >> 4) % nheads;
    int s = idx / (16 * nheads);

    const float LOG2_BASE = 18.93156856932417f;   // log2(500000)
    const float TWO_PI    = 6.283185307179586f;

    float* row = x + (size_t)s * nheads * HD + h * HD;
    float4 v1 = *(float4*)&row[g * 4];
    float4 v2 = *(float4*)&row[g * 4 + 64];

    float o1[4], o2[4];
#pragma unroll
    for (int t = 0; t < 4; t++) {
        int i = g * 4 + t;
        float inv_freq = exp2f(-((float)(2 * i) / 128.0f) * LOG2_BASE);
        float wavelen  = TWO_PI / inv_freq;
        float smooth   = (8192.0f / wavelen - 1.0f) * (1.0f / 3.0f);
        smooth = fminf(1.0f, fmaxf(0.0f, smooth));
        float freq = (1.0f - smooth) * (inv_freq * 0.125f) + smooth * inv_freq;

        float c, sn;
        sincosf((float)s * freq, &sn, &c);
        float x1 = (&v1.x)[t], x2 = (&v2.x)[t];
        o1[t] = x1 * c - x2 * sn;
        o2[t] = x2 * c + x1 * sn;
    }
    *(float4*)&row[g * 4]      = make_float4(o1[0], o1[1], o1[2], o1[3]);
    *(float4*)&row[g * 4 + 64] = make_float4(o2[0], o2[1], o2[2], o2[3]);
}

// ================= Flash attention (causal, GQA), fp32 =================
#define BQ 64
#define BKV 64
#define KSTR 132
#define PSTR 65

__global__ __launch_bounds__(256, 1)
void flash_kernel(const float* __restrict__ Q, const float* __restrict__ K,
                  const float* __restrict__ V, float* __restrict__ O)
{
    extern __shared__ float sm[];
    float* Qs  = sm;                       // [64][132]
    float* KVs = sm + 64 * KSTR;           // [64][132]
    float* Ps  = sm + 2 * 64 * KSTR;       // [64][65]

    const int qt  = gridDim.x - 1 - blockIdx.x;
    const int h   = blockIdx.y;
    const int kvh = h >> 2;
    const int tid = threadIdx.x;
    const int tx = tid & 15, ty = tid >> 4;
    const int q0 = qt * BQ;
    const float scale = 0.08838834764831845f;

    for (int t = tid; t < 64 * 32; t += 256) {
        int r = t >> 5, c4 = (t & 31) << 2;
        *(float4*)&Qs[r * KSTR + c4] =
            *(const float4*)&Q[(size_t)(q0 + r) * (NH * HD) + h * HD + c4];
    }

    float m_i[4], l_i[4], o_acc[4][8];
#pragma unroll
    for (int i = 0; i < 4; i++) {
        m_i[i] = -INFINITY;
        l_i[i] = 0.f;
#pragma unroll
        for (int j = 0; j < 8; j++) o_acc[i][j] = 0.f;
    }

    for (int j = 0; j <= qt; j++) {
        const int k0 = j * BKV;
        __syncthreads();
        for (int t = tid; t < 64 * 32; t += 256) {
            int r = t >> 5, c4 = (t & 31) << 2;
            *(float4*)&KVs[r * KSTR + c4] =
                *(const float4*)&K[(size_t)(k0 + r) * (NKV * HD) + kvh * HD + c4];
        }
        __syncthreads();

        float sacc[4][4];
#pragma unroll
        for (int i = 0; i < 4; i++)
#pragma unroll
            for (int jj = 0; jj < 4; jj++) sacc[i][jj] = 0.f;

#pragma unroll 8
        for (int d = 0; d < HD; d += 4) {
            float4 qa[4], kb[4];
#pragma unroll
            for (int i = 0; i < 4; i++)
                qa[i] = *(const float4*)&Qs[(ty * 4 + i) * KSTR + d];
#pragma unroll
            for (int i = 0; i < 4; i++)
                kb[i] = *(const float4*)&KVs[(tx * 4 + i) * KSTR + d];
#pragma unroll
            for (int i = 0; i < 4; i++)
#pragma unroll
                for (int jj = 0; jj < 4; jj++) {
                    sacc[i][jj] = fmaf(qa[i].x, kb[jj].x, sacc[i][jj]);
                    sacc[i][jj] = fmaf(qa[i].y, kb[jj].y, sacc[i][jj]);
                    sacc[i][jj] = fmaf(qa[i].z, kb[jj].z, sacc[i][jj]);
                    sacc[i][jj] = fmaf(qa[i].w, kb[jj].w, sacc[i][jj]);
                }
        }

        const bool diag = (j == qt);
#pragma unroll
        for (int i = 0; i < 4; i++)
#pragma unroll
            for (int jj = 0; jj < 4; jj++) {
                float v = sacc[i][jj] * scale;
                if (diag && (k0 + tx * 4 + jj) > (q0 + ty * 4 + i)) v = -INFINITY;
                sacc[i][jj] = v;
            }

        float mt[4], mn[4], alpha[4], rs[4];
#pragma unroll
        for (int i = 0; i < 4; i++) {
            mt[i] = fmaxf(fmaxf(sacc[i][0], sacc[i][1]), fmaxf(sacc[i][2], sacc[i][3]));
#pragma unroll
            for (int off = 8; off >= 1; off >>= 1)
                mt[i] = fmaxf(mt[i], __shfl_xor_sync(0xffffffffu, mt[i], off, 16));
            mn[i]    = fmaxf(m_i[i], mt[i]);
            alpha[i] = expf(m_i[i] - mn[i]);
            float lsum = 0.f;
#pragma unroll
            for (int jj = 0; jj < 4; jj++) {
                float p = expf(sacc[i][jj] - mn[i]);
                sacc[i][jj] = p;
                lsum += p;
            }
#pragma unroll
            for (int off = 8; off >= 1; off >>= 1)
                lsum += __shfl_xor_sync(0xffffffffu, lsum, off, 16);
            rs[i] = lsum;
        }
#pragma unroll
        for (int i = 0; i < 4; i++) {
            l_i[i] = l_i[i] * alpha[i] + rs[i];
            m_i[i] = mn[i];
#pragma unroll
            for (int jj = 0; jj < 8; jj++) o_acc[i][jj] *= alpha[i];
#pragma unroll
            for (int jj = 0; jj < 4; jj++)
                Ps[(ty * 4 + i) * PSTR + tx * 4 + jj] = sacc[i][jj];
        }
        __syncthreads();

        for (int t = tid; t < 64 * 32; t += 256) {
            int r = t >> 5, c4 = (t & 31) << 2;
            *(float4*)&KVs[r * KSTR + c4] =
                *(const float4*)&V[(size_t)(k0 + r) * (NKV * HD) + kvh * HD + c4];
        }
        __syncthreads();

#pragma unroll 4
        for (int c = 0; c < BKV; c++) {
            float4 v0 = *(const float4*)&KVs[c * KSTR + tx * 8];
            float4 v1 = *(const float4*)&KVs[c * KSTR + tx * 8 + 4];
#pragma unroll
            for (int i = 0; i < 4; i++) {
                float p = Ps[(ty * 4 + i) * PSTR + c];
                o_acc[i][0] = fmaf(p, v0.x, o_acc[i][0]);
                o_acc[i][1] = fmaf(p, v0.y, o_acc[i][1]);
                o_acc[i][2] = fmaf(p, v0.z, o_acc[i][2]);
                o_acc[i][3] = fmaf(p, v0.w, o_acc[i][3]);
                o_acc[i][4] = fmaf(p, v1.x, o_acc[i][4]);
                o_acc[i][5] = fmaf(p, v1.y, o_acc[i][5]);
                o_acc[i][6] = fmaf(p, v1.z, o_acc[i][6]);
                o_acc[i][7] = fmaf(p, v1.w, o_acc[i][7]);
            }
        }
    }

#pragma unroll
    for (int i = 0; i < 4; i++) {
        float inv = 1.f / l_i[i];
        float* Orow = O + (size_t)(q0 + ty * 4 + i) * (NH * HD) + h * HD + tx * 8;
        *(float4*)(Orow)     = make_float4(o_acc[i][0] * inv, o_acc[i][1] * inv,
                                           o_acc[i][2] * inv, o_acc[i][3] * inv);
        *(float4*)(Orow + 4) = make_float4(o_acc[i][4] * inv, o_acc[i][5] * inv,
                                           o_acc[i][6] * inv, o_acc[i][7] * inv);
    }
}

// ================= launcher =================
extern "C" void kernel_launch(void* const* d_in, const int* in_sizes, int n_in,
                              void* d_out, int out_size)
{
    const float* X  = (const float*)d_in[0];
    const float* Wq = (const float*)d_in[1];
    const float* Wk = (const float*)d_in[2];
    const float* Wv = (const float*)d_in[3];
    const float* Wo = (const float*)d_in[4];
    float* out = (float*)d_out;

    float *Qp, *Kp, *Vp, *Ap;
    cudaGetSymbolAddress((void**)&Qp, g_Q);
    cudaGetSymbolAddress((void**)&Kp, g_K);
    cudaGetSymbolAddress((void**)&Vp, g_V);
    cudaGetSymbolAddress((void**)&Ap, g_attn);

    dim3 blk(256);
    const int gemm_smem = NSTAGE * STAGE_ELEMS * (int)sizeof(float);  // 56832 B
    cudaFuncSetAttribute(sgemm_tf32,     cudaFuncAttributeMaxDynamicSharedMemorySize, gemm_smem);
    cudaFuncSetAttribute(sgemm_tf32_qkv, cudaFuncAttributeMaxDynamicSharedMemorySize, gemm_smem);

    // fused QKV projection: 48 x 16 CTAs, one launch
    sgemm_tf32_qkv<<<dim3(48, S_LEN / 128), blk, gemm_smem>>>(X, Wq, Wk, Wv, Qp, Kp, Vp);

    // RoPE on Q and K
    int tq = S_LEN * NH * 16;
    int tk = S_LEN * NKV * 16;
    rope_kernel<<<(tq + 255) / 256, 256>>>(Qp, NH);
    rope_kernel<<<(tk + 255) / 256, 256>>>(Kp, NKV);

    // flash attention (fp32)
    const int smem = (2 * 64 * KSTR + 64 * PSTR) * (int)sizeof(float);  // 84224 B
    cudaFuncSetAttribute(flash_kernel, cudaFuncAttributeMaxDynamicSharedMemorySize, smem);
    flash_kernel<<<dim3(S_LEN / BQ, NH), blk, smem>>>(Qp, Kp, Vp, Ap);

    // output projection (tf32 tensor cores)
    sgemm_tf32<<<dim3(HID / 128, S_LEN / 128), blk, gemm_smem>>>(Ap, Wo, out, S_LEN, HID, HID);
}

// round 12
// speedup vs baseline: 2.5280x; 1.1953x over previous
#include <cuda_runtime.h>
#include <math.h>
#include <stdint.h>

#define S_LEN 2048
#define HID   4096
#define NH    32
#define NKV   8
#define HD    128

// -------- scratch (device globals; no allocation allowed) --------
__device__ float g_Q[S_LEN * NH * HD];     // 32 MB
__device__ float g_K[S_LEN * NKV * HD];    // 8 MB
__device__ float g_V[S_LEN * NKV * HD];    // 8 MB
__device__ float g_attn[S_LEN * NH * HD];  // 32 MB

// ---------------- tf32 helpers ----------------
__device__ __forceinline__ uint32_t frag_tf32(float x) {
    uint32_t u;
    asm("cvt.rna.tf32.f32 %0, %1;" : "=r"(u) : "f"(x));
    return u;
}

__device__ __forceinline__ void mma_tf32(float& d0, float& d1, float& d2, float& d3,
                                         uint32_t a0, uint32_t a1, uint32_t a2, uint32_t a3,
                                         uint32_t b0, uint32_t b1) {
    asm volatile(
        "mma.sync.aligned.m16n8k8.row.col.f32.tf32.tf32.f32 "
        "{%0,%1,%2,%3}, {%4,%5,%6,%7}, {%8,%9}, {%0,%1,%2,%3};"
        : "+f"(d0), "+f"(d1), "+f"(d2), "+f"(d3)
        : "r"(a0), "r"(a1), "r"(a2), "r"(a3), "r"(b0), "r"(b1));
}

__device__ __forceinline__ void cp_async16(uint32_t smem_addr, const void* gptr) {
    asm volatile("cp.async.cg.shared.global [%0], [%1], 16;\n"
                 :: "r"(smem_addr), "l"(gptr));
}
__device__ __forceinline__ void cp_commit() {
    asm volatile("cp.async.commit_group;\n" ::: "memory");
}
template <int N>
__device__ __forceinline__ void cp_wait() {
    asm volatile("cp.async.wait_group %0;\n" :: "n"(N) : "memory");
}

// ============ TF32 GEMM core (shared by generic + fused-QKV kernels) ============
#define APITCH 20
#define BPITCH 136
#define A_ELEMS (128 * APITCH)
#define B_ELEMS (16 * BPITCH)
#define STAGE_ELEMS (A_ELEMS + B_ELEMS)
#define NSTAGE 3

__device__ __forceinline__ void gemm_tile_tf32(
    const float* __restrict__ Ag0, int K,
    const float* __restrict__ Bg0, int NB,
    float* __restrict__ Ct, int NC, float* smem)
{
    const int tid  = threadIdx.x;
    const int lane = tid & 31;
    const int wid  = tid >> 5;
    const int warp_m = wid & 1;
    const int warp_n = wid >> 1;
    const int r = lane >> 2;
    const int c = lane & 3;

    const int am  = tid >> 1;
    const int ak8 = (tid & 1) * 8;
    const int bk  = tid >> 4;
    const int bn0 = (tid & 15) * 8;

    const float* Ag = Ag0 + (size_t)am * K + ak8;
    const float* Bg = Bg0 + (size_t)bk * NB + bn0;

    uint32_t smem_base;
    asm("{ .reg .u64 t; cvta.to.shared.u64 t, %1; cvt.u32.u64 %0, t; }"
        : "=r"(smem_base) : "l"(smem));

    float acc[4][4][4];
#pragma unroll
    for (int f = 0; f < 4; f++)
#pragma unroll
        for (int g = 0; g < 4; g++)
#pragma unroll
            for (int x = 0; x < 4; x++) acc[f][g][x] = 0.f;

    const int ntiles = K >> 4;

#pragma unroll
    for (int pf = 0; pf < 2; pf++) {
        uint32_t sa = smem_base + (pf * STAGE_ELEMS + am * APITCH + ak8) * 4;
        cp_async16(sa,      Ag + (size_t)pf * 16);
        cp_async16(sa + 16, Ag + (size_t)pf * 16 + 4);
        uint32_t sb = smem_base + (pf * STAGE_ELEMS + A_ELEMS + bk * BPITCH + bn0) * 4;
        cp_async16(sb,      Bg + (size_t)pf * 16 * NB);
        cp_async16(sb + 16, Bg + (size_t)pf * 16 * NB + 4);
        cp_commit();
    }

    for (int kt = 0; kt < ntiles; kt++) {
        cp_wait<1>();
        __syncthreads();

        if (kt + 2 < ntiles) {
            int st = (kt + 2) % NSTAGE;
            uint32_t sa = smem_base + (st * STAGE_ELEMS + am * APITCH + ak8) * 4;
            cp_async16(sa,      Ag + (size_t)(kt + 2) * 16);
            cp_async16(sa + 16, Ag + (size_t)(kt + 2) * 16 + 4);
            uint32_t sb = smem_base + (st * STAGE_ELEMS + A_ELEMS + bk * BPITCH + bn0) * 4;
            cp_async16(sb,      Bg + (size_t)(kt + 2) * 16 * NB);
            cp_async16(sb + 16, Bg + (size_t)(kt + 2) * 16 * NB + 4);
        }
        cp_commit();

        const float* As = smem + (kt % NSTAGE) * STAGE_ELEMS;
        const float* Bs = As + A_ELEMS;

#pragma unroll
        for (int s = 0; s < 2; s++) {
            const int k0 = s * 8;
            uint32_t af[4][4], bf[4][2];
#pragma unroll
            for (int f = 0; f < 4; f++) {
                const int mb = warp_m * 64 + f * 16;
                af[f][0] = frag_tf32(As[(mb + r    ) * APITCH + k0 + c    ]);
                af[f][1] = frag_tf32(As[(mb + r + 8) * APITCH + k0 + c    ]);
                af[f][2] = frag_tf32(As[(mb + r    ) * APITCH + k0 + c + 4]);
                af[f][3] = frag_tf32(As[(mb + r + 8) * APITCH + k0 + c + 4]);
            }
#pragma unroll
            for (int g = 0; g < 4; g++) {
                const int nb = warp_n * 32 + g * 8;
                bf[g][0] = frag_tf32(Bs[(k0 + c    ) * BPITCH + nb + r]);
                bf[g][1] = frag_tf32(Bs[(k0 + c + 4) * BPITCH + nb + r]);
            }
#pragma unroll
            for (int f = 0; f < 4; f++)
#pragma unroll
                for (int g = 0; g < 4; g++)
                    mma_tf32(acc[f][g][0], acc[f][g][1], acc[f][g][2], acc[f][g][3],
                             af[f][0], af[f][1], af[f][2], af[f][3],
                             bf[g][0], bf[g][1]);
        }
    }

#pragma unroll
    for (int f = 0; f < 4; f++) {
        const int row0 = warp_m * 64 + f * 16 + r;
#pragma unroll
        for (int g = 0; g < 4; g++) {
            const int col0 = warp_n * 32 + g * 8 + 2 * c;
            *(float2*)&Ct[(size_t)row0 * NC + col0]       = make_float2(acc[f][g][0], acc[f][g][1]);
            *(float2*)&Ct[(size_t)(row0 + 8) * NC + col0] = make_float2(acc[f][g][2], acc[f][g][3]);
        }
    }
}

__global__ __launch_bounds__(256, 2)
void sgemm_tf32(const float* __restrict__ A, const float* __restrict__ B,
                float* __restrict__ C, int M, int N, int K)
{
    extern __shared__ float smem[];
    const int bn = blockIdx.x, bm = blockIdx.y;
    gemm_tile_tf32(A + (size_t)bm * 128 * K, K,
                   B + (size_t)bn * 128, N,
                   C + (size_t)bm * 128 * N + (size_t)bn * 128, N, smem);
}

__global__ __launch_bounds__(256, 2)
void sgemm_tf32_qkv(const float* __restrict__ X,
                    const float* __restrict__ Wq, const float* __restrict__ Wk,
                    const float* __restrict__ Wv,
                    float* __restrict__ Qo, float* __restrict__ Ko,
                    float* __restrict__ Vo)
{
    extern __shared__ float smem[];
    const int bn = blockIdx.x, bm = blockIdx.y;

    const float* Bb;
    float* Cb;
    int Nw, bnl;
    if (bn < 32)      { Bb = Wq; Cb = Qo; Nw = NH * HD;  bnl = bn; }
    else if (bn < 40) { Bb = Wk; Cb = Ko; Nw = NKV * HD; bnl = bn - 32; }
    else              { Bb = Wv; Cb = Vo; Nw = NKV * HD; bnl = bn - 40; }

    gemm_tile_tf32(X + (size_t)bm * 128 * HID, HID,
                   Bb + (size_t)bnl * 128, Nw,
                   Cb + (size_t)bm * 128 * Nw + (size_t)bnl * 128, Nw, smem);
}

// ================= llama3-smoothed RoPE, in place, fp32, float4 =================
__global__ __launch_bounds__(256)
void rope_kernel(float* __restrict__ x, int nheads)
{
    int idx = blockIdx.x * blockDim.x + threadIdx.x;
    int total = S_LEN * nheads * 16;
    if (idx >= total) return;
    int g = idx & 15;
    int h = (idx >> 4) % nheads;
    int s = idx / (16 * nheads);

    const float LOG2_BASE = 18.93156856932417f;   // log2(500000)
    const float TWO_PI    = 6.283185307179586f;

    float* row = x + (size_t)s * nheads * HD + h * HD;
    float4 v1 = *(float4*)&row[g * 4];
    float4 v2 = *(float4*)&row[g * 4 + 64];

    float o1[4], o2[4];
#pragma unroll
    for (int t = 0; t < 4; t++) {
        int i = g * 4 + t;
        float inv_freq = exp2f(-((float)(2 * i) / 128.0f) * LOG2_BASE);
        float wavelen  = TWO_PI / inv_freq;
        float smooth   = (8192.0f / wavelen - 1.0f) * (1.0f / 3.0f);
        smooth = fminf(1.0f, fmaxf(0.0f, smooth));
        float freq = (1.0f - smooth) * (inv_freq * 0.125f) + smooth * inv_freq;

        float c, sn;
        sincosf((float)s * freq, &sn, &c);
        float x1 = (&v1.x)[t], x2 = (&v2.x)[t];
        o1[t] = x1 * c - x2 * sn;
        o2[t] = x2 * c + x1 * sn;
    }
    *(float4*)&row[g * 4]      = make_float4(o1[0], o1[1], o1[2], o1[3]);
    *(float4*)&row[g * 4 + 64] = make_float4(o2[0], o2[1], o2[2], o2[3]);
}

// ================= Flash attention (causal, GQA), fp32, BQ=128 =================
// grid: (16 q-tiles, 32 heads), 256 threads (16x16). Thread tile: QK 8x4, PV 8x8.
// smem: Qs[128][132], KVs[64][132] (K then V), Ps[128][65]  -> 134656 B
#define BQ 128
#define BKV 64
#define KSTR 132
#define PSTR 65

__global__ __launch_bounds__(256, 1)
void flash_kernel(const float* __restrict__ Q, const float* __restrict__ K,
                  const float* __restrict__ V, float* __restrict__ O)
{
    extern __shared__ float sm[];
    float* Qs  = sm;                         // [128][132]
    float* KVs = sm + BQ * KSTR;             // [64][132]
    float* Ps  = sm + BQ * KSTR + BKV * KSTR;// [128][65]

    const int qt  = gridDim.x - 1 - blockIdx.x;   // longest blocks first
    const int h   = blockIdx.y;
    const int kvh = h >> 2;
    const int tid = threadIdx.x;
    const int tx = tid & 15, ty = tid >> 4;
    const int q0 = qt * BQ;
    const float scale = 0.08838834764831845f;

    // load Q tile (coalesced float4): 128 rows x 32 float4
    for (int t = tid; t < BQ * 32; t += 256) {
        int r = t >> 5, c4 = (t & 31) << 2;
        *(float4*)&Qs[r * KSTR + c4] =
            *(const float4*)&Q[(size_t)(q0 + r) * (NH * HD) + h * HD + c4];
    }

    float m_i[8], l_i[8], o_acc[8][8];
#pragma unroll
    for (int i = 0; i < 8; i++) {
        m_i[i] = -INFINITY;
        l_i[i] = 0.f;
#pragma unroll
        for (int j = 0; j < 8; j++) o_acc[i][j] = 0.f;
    }

    const int njt = 2 * qt + 2;   // kv tiles of 64 covering q0+127
    for (int j = 0; j < njt; j++) {
        const int k0 = j * BKV;
        __syncthreads();   // prev PV done reading KVs; Qs ready (iter 0)
        for (int t = tid; t < BKV * 32; t += 256) {
            int r = t >> 5, c4 = (t & 31) << 2;
            *(float4*)&KVs[r * KSTR + c4] =
                *(const float4*)&K[(size_t)(k0 + r) * (NKV * HD) + kvh * HD + c4];
        }
        __syncthreads();

        // ---- S = Q K^T (8x4 per thread) ----
        float sacc[8][4];
#pragma unroll
        for (int i = 0; i < 8; i++)
#pragma unroll
            for (int jj = 0; jj < 4; jj++) sacc[i][jj] = 0.f;

#pragma unroll 4
        for (int d = 0; d < HD; d += 4) {
            float4 qa[8], kb[4];
#pragma unroll
            for (int i = 0; i < 8; i++)
                qa[i] = *(const float4*)&Qs[(ty * 8 + i) * KSTR + d];
#pragma unroll
            for (int i = 0; i < 4; i++)
                kb[i] = *(const float4*)&KVs[(tx * 4 + i) * KSTR + d];
#pragma unroll
            for (int i = 0; i < 8; i++)
#pragma unroll
                for (int jj = 0; jj < 4; jj++) {
                    sacc[i][jj] = fmaf(qa[i].x, kb[jj].x, sacc[i][jj]);
                    sacc[i][jj] = fmaf(qa[i].y, kb[jj].y, sacc[i][jj]);
                    sacc[i][jj] = fmaf(qa[i].z, kb[jj].z, sacc[i][jj]);
                    sacc[i][jj] = fmaf(qa[i].w, kb[jj].w, sacc[i][jj]);
                }
        }

        // ---- scale + causal mask (last two tiles only) ----
        const bool diag = (j >= njt - 2);
#pragma unroll
        for (int i = 0; i < 8; i++)
#pragma unroll
            for (int jj = 0; jj < 4; jj++) {
                float v = sacc[i][jj] * scale;
                if (diag && (k0 + tx * 4 + jj) > (q0 + ty * 8 + i)) v = -INFINITY;
                sacc[i][jj] = v;
            }

        // ---- online softmax (reduce over tx: xor 8,4,2,1 within half-warp) ----
#pragma unroll
        for (int i = 0; i < 8; i++) {
            float mt = fmaxf(fmaxf(sacc[i][0], sacc[i][1]), fmaxf(sacc[i][2], sacc[i][3]));
#pragma unroll
            for (int off = 8; off >= 1; off >>= 1)
                mt = fmaxf(mt, __shfl_xor_sync(0xffffffffu, mt, off, 16));
            float mn    = fmaxf(m_i[i], mt);
            float alpha = expf(m_i[i] - mn);
            float lsum = 0.f;
#pragma unroll
            for (int jj = 0; jj < 4; jj++) {
                float p = expf(sacc[i][jj] - mn);
                sacc[i][jj] = p;
                lsum += p;
            }
#pragma unroll
            for (int off = 8; off >= 1; off >>= 1)
                lsum += __shfl_xor_sync(0xffffffffu, lsum, off, 16);
            l_i[i] = l_i[i] * alpha + lsum;
            m_i[i] = mn;
#pragma unroll
            for (int jj = 0; jj < 8; jj++) o_acc[i][jj] *= alpha;
#pragma unroll
            for (int jj = 0; jj < 4; jj++)
                Ps[(ty * 8 + i) * PSTR + tx * 4 + jj] = sacc[i][jj];
        }
        __syncthreads();   // Ps visible; all K reads done

        // ---- load V over KVs ----
        for (int t = tid; t < BKV * 32; t += 256) {
            int r = t >> 5, c4 = (t & 31) << 2;
            *(float4*)&KVs[r * KSTR + c4] =
                *(const float4*)&V[(size_t)(k0 + r) * (NKV * HD) + kvh * HD + c4];
        }
        __syncthreads();

        // ---- O += P @ V (8 rows x 8 dims per thread) ----
#pragma unroll 4
        for (int c = 0; c < BKV; c++) {
            float4 v0 = *(const float4*)&KVs[c * KSTR + tx * 8];
            float4 v1 = *(const float4*)&KVs[c * KSTR + tx * 8 + 4];
#pragma unroll
            for (int i = 0; i < 8; i++) {
                float p = Ps[(ty * 8 + i) * PSTR + c];
                o_acc[i][0] = fmaf(p, v0.x, o_acc[i][0]);
                o_acc[i][1] = fmaf(p, v0.y, o_acc[i][1]);
                o_acc[i][2] = fmaf(p, v0.z, o_acc[i][2]);
                o_acc[i][3] = fmaf(p, v0.w, o_acc[i][3]);
                o_acc[i][4] = fmaf(p, v1.x, o_acc[i][4]);
                o_acc[i][5] = fmaf(p, v1.y, o_acc[i][5]);
                o_acc[i][6] = fmaf(p, v1.z, o_acc[i][6]);
                o_acc[i][7] = fmaf(p, v1.w, o_acc[i][7]);
            }
        }
    }

    // ---- epilogue: O / l ----
#pragma unroll
    for (int i = 0; i < 8; i++) {
        float inv = 1.f / l_i[i];
        float* Orow = O + (size_t)(q0 + ty * 8 + i) * (NH * HD) + h * HD + tx * 8;
        *(float4*)(Orow)     = make_float4(o_acc[i][0] * inv, o_acc[i][1] * inv,
                                           o_acc[i][2] * inv, o_acc[i][3] * inv);
        *(float4*)(Orow + 4) = make_float4(o_acc[i][4] * inv, o_acc[i][5] * inv,
                                           o_acc[i][6] * inv, o_acc[i][7] * inv);
    }
}

// ================= launcher =================
extern "C" void kernel_launch(void* const* d_in, const int* in_sizes, int n_in,
                              void* d_out, int out_size)
{
    const float* X  = (const float*)d_in[0];
    const float* Wq = (const float*)d_in[1];
    const float* Wk = (const float*)d_in[2];
    const float* Wv = (const float*)d_in[3];
    const float* Wo = (const float*)d_in[4];
    float* out = (float*)d_out;

    float *Qp, *Kp, *Vp, *Ap;
    cudaGetSymbolAddress((void**)&Qp, g_Q);
    cudaGetSymbolAddress((void**)&Kp, g_K);
    cudaGetSymbolAddress((void**)&Vp, g_V);
    cudaGetSymbolAddress((void**)&Ap, g_attn);

    dim3 blk(256);
    const int gemm_smem = NSTAGE * STAGE_ELEMS * (int)sizeof(float);  // 56832 B
    cudaFuncSetAttribute(sgemm_tf32,     cudaFuncAttributeMaxDynamicSharedMemorySize, gemm_smem);
    cudaFuncSetAttribute(sgemm_tf32_qkv, cudaFuncAttributeMaxDynamicSharedMemorySize, gemm_smem);

    // fused QKV projection
    sgemm_tf32_qkv<<<dim3(48, S_LEN / 128), blk, gemm_smem>>>(X, Wq, Wk, Wv, Qp, Kp, Vp);

    // RoPE on Q and K
    int tq = S_LEN * NH * 16;
    int tk = S_LEN * NKV * 16;
    rope_kernel<<<(tq + 255) / 256, 256>>>(Qp, NH);
    rope_kernel<<<(tk + 255) / 256, 256>>>(Kp, NKV);

    // flash attention (fp32, BQ=128)
    const int fsmem = (BQ * KSTR + BKV * KSTR + BQ * PSTR) * (int)sizeof(float);  // 134656 B
    cudaFuncSetAttribute(flash_kernel, cudaFuncAttributeMaxDynamicSharedMemorySize, fsmem);
    flash_kernel<<<dim3(S_LEN / BQ, NH), blk, fsmem>>>(Qp, Kp, Vp, Ap);

    // output projection
    sgemm_tf32<<<dim3(HID / 128, S_LEN / 128), blk, gemm_smem>>>(Ap, Wo, out, S_LEN, HID, HID);
}